// round 11
// baseline (speedup 1.0000x reference)
#include <cuda_runtime.h>
#include <cuda_bf16.h>

// Problem constants
#define BB 16
#define LL 512
#define HS 1024
#define HH 16
#define DD 64
#define MROWS (BB*LL)        // 8192

// -------------------- scratch (allocation-free) --------------------
__device__ float g_vh[BB*HH*LL*DD];   // [B,H,L,D]
__device__ float g_kh[BB*HH*LL*DD];
__device__ float g_qh[BB*HH*LL*DD];
__device__ float g_qn[BB*HH*LL*DD];   // modulated q
__device__ unsigned char g_absm8[BB*LL*LL];   // packed masks (1 byte/elem)
__device__ unsigned char g_mask8[BB*LL*LL];
// pre-split bf16 operands (uint4 for 16B alignment)
__device__ uint4 g_inhi[3L*MROWS*HS/8];   // v,k,q hi
__device__ uint4 g_inlo[3L*MROWS*HS/8];   // v,k,q lo
__device__ uint4 g_whi[4L*HS*HS/8];       // Wv,Wk,Wq,Wm hi
__device__ uint4 g_wlo[4L*HS*HS/8];
__device__ uint4 g_atthi[(long)MROWS*HS/8];  // attn output hi
__device__ uint4 g_attlo[(long)MROWS*HS/8];

// ------------------ bf16 helpers ------------------
__device__ __forceinline__ unsigned pack2bf(__nv_bfloat16 a, __nv_bfloat16 b) {
    __nv_bfloat162 t; t.x = a; t.y = b;
    return reinterpret_cast<unsigned&>(t);
}

__device__ __forceinline__ void bsplit2(float x0, float x1, unsigned &hi, unsigned &lo) {
    __nv_bfloat16 h0 = __float2bfloat16(x0);
    __nv_bfloat16 h1 = __float2bfloat16(x1);
    __nv_bfloat16 l0 = __float2bfloat16(x0 - __bfloat162float(h0));
    __nv_bfloat16 l1 = __float2bfloat16(x1 - __bfloat162float(h1));
    hi = pack2bf(h0, h1);
    lo = pack2bf(l0, l1);
}

__device__ __forceinline__ void mma_bf16(float d[4],
                                         unsigned a0, unsigned a1, unsigned a2, unsigned a3,
                                         unsigned b0, unsigned b1)
{
    asm volatile(
        "mma.sync.aligned.m16n8k16.row.col.f32.bf16.bf16.f32 "
        "{%0,%1,%2,%3}, {%4,%5,%6,%7}, {%8,%9}, {%0,%1,%2,%3};\n"
        : "+f"(d[0]), "+f"(d[1]), "+f"(d[2]), "+f"(d[3])
        : "r"(a0), "r"(a1), "r"(a2), "r"(a3), "r"(b0), "r"(b1));
}

// ====================================================================
// Prepack kernels
// ====================================================================
__global__ void __launch_bounds__(256) pack_masks(const uint4* __restrict__ a,
                                                  const uint4* __restrict__ b,
                                                  uchar4* __restrict__ oa,
                                                  uchar4* __restrict__ ob)
{
    int i = blockIdx.x * blockDim.x + threadIdx.x;
    uint4 x = a[i];
    oa[i] = make_uchar4(x.x ? 1 : 0, x.y ? 1 : 0, x.z ? 1 : 0, x.w ? 1 : 0);
    uint4 y = b[i];
    ob[i] = make_uchar4(y.x ? 1 : 0, y.y ? 1 : 0, y.z ? 1 : 0, y.w ? 1 : 0);
}

__global__ void __launch_bounds__(256) pack_in(const float4* __restrict__ v,
                                               const float4* __restrict__ k,
                                               const float4* __restrict__ q)
{
    int z = blockIdx.y;
    const float4* src = (z == 0) ? v : (z == 1) ? k : q;
    long i = (long)blockIdx.x * 256 + threadIdx.x;
    float4 x = src[i];
    unsigned h01, l01, h23, l23;
    bsplit2(x.x, x.y, h01, l01);
    bsplit2(x.z, x.w, h23, l23);
    long d = (long)z * (MROWS * (long)HS / 4) + i;
    ((uint2*)g_inhi)[d] = make_uint2(h01, h23);
    ((uint2*)g_inlo)[d] = make_uint2(l01, l23);
}

__global__ void __launch_bounds__(256) pack_w(const float4* __restrict__ w0,
                                              const float4* __restrict__ w1,
                                              const float4* __restrict__ w2,
                                              const float4* __restrict__ w3)
{
    int z = blockIdx.y;
    const float4* src = (z == 0) ? w0 : (z == 1) ? w1 : (z == 2) ? w2 : w3;
    long i = (long)blockIdx.x * 256 + threadIdx.x;
    float4 x = src[i];
    unsigned h01, l01, h23, l23;
    bsplit2(x.x, x.y, h01, l01);
    bsplit2(x.z, x.w, h23, l23);
    long d = (long)z * ((long)HS * HS / 4) + i;
    ((uint2*)g_whi)[d] = make_uint2(h01, h23);
    ((uint2*)g_wlo)[d] = make_uint2(l01, l23);
}

// ====================================================================
// bf16 GEMM, 3-term compensation, pre-split operands, 2-stage pipeline.
// R11: mma issue reordered term-outer (same-acc distance 3 -> 16).
// ====================================================================
#define BP 40
#define GST (4*128*BP)

template<int GEMM3>
__global__ void __launch_bounds__(256, 1) gemm_pre(float* __restrict__ Cout,
                                                   int M, int N, int K)
{
    extern __shared__ float smf[];
    __nv_bfloat16* smb = (__nv_bfloat16*)smf;

    const __nv_bfloat16 *Ahi, *Alo, *Whi, *Wlo;
    float* C;
    if (GEMM3) {
        int z = blockIdx.z;
        Ahi = (const __nv_bfloat16*)g_inhi + (long)z * MROWS * HS;
        Alo = (const __nv_bfloat16*)g_inlo + (long)z * MROWS * HS;
        Whi = (const __nv_bfloat16*)g_whi + (long)z * HS * HS;
        Wlo = (const __nv_bfloat16*)g_wlo + (long)z * HS * HS;
        C   = (z == 0) ? g_vh : (z == 1) ? g_kh : g_qh;
    } else {
        Ahi = (const __nv_bfloat16*)g_atthi;
        Alo = (const __nv_bfloat16*)g_attlo;
        Whi = (const __nv_bfloat16*)g_whi + 3L * HS * HS;
        Wlo = (const __nv_bfloat16*)g_wlo + 3L * HS * HS;
        C   = Cout;
    }

    const int tid  = threadIdx.x;
    const int br   = blockIdx.y;
    const int bc   = blockIdx.x;
    const int wid  = tid >> 5;
    const int lane = tid & 31;
    const int g    = lane >> 2;
    const int tig  = lane & 3;
    const int wm   = wid >> 2;
    const int wn   = wid & 3;

    const __nv_bfloat16* AbH = Ahi + (long)br * 128 * K;
    const __nv_bfloat16* AbL = Alo + (long)br * 128 * K;
    const __nv_bfloat16* BbH = Whi + (long)bc * 128 * K;
    const __nv_bfloat16* BbL = Wlo + (long)bc * 128 * K;

    float acc[4][4][4];
#pragma unroll
    for (int mt = 0; mt < 4; ++mt)
#pragma unroll
        for (int nt = 0; nt < 4; ++nt)
#pragma unroll
            for (int r = 0; r < 4; ++r) acc[mt][nt][r] = 0.f;

    const int r0c = tid >> 2;
    const int c0c = tid & 3;
    const int r1c = (tid + 256) >> 2;
    const int c1c = c0c;

    uint4 pAH[2], pAL[2], pBH[2], pBL[2];

    auto fetch = [&](int kb) {
        const long o0 = (long)r0c * K + kb + c0c * 8;
        const long o1 = (long)r1c * K + kb + c1c * 8;
        pAH[0] = *(const uint4*)(AbH + o0);
        pAH[1] = *(const uint4*)(AbH + o1);
        pAL[0] = *(const uint4*)(AbL + o0);
        pAL[1] = *(const uint4*)(AbL + o1);
        pBH[0] = *(const uint4*)(BbH + o0);
        pBH[1] = *(const uint4*)(BbH + o1);
        pBL[0] = *(const uint4*)(BbL + o0);
        pBL[1] = *(const uint4*)(BbL + o1);
    };
    auto store_tile = [&](int s) {
        __nv_bfloat16* AsHi = smb + s * GST;
        __nv_bfloat16* AsLo = AsHi + 128 * BP;
        __nv_bfloat16* BsHi = AsLo + 128 * BP;
        __nv_bfloat16* BsLo = BsHi + 128 * BP;
        *(uint4*)(AsHi + r0c * BP + c0c * 8) = pAH[0];
        *(uint4*)(AsHi + r1c * BP + c1c * 8) = pAH[1];
        *(uint4*)(AsLo + r0c * BP + c0c * 8) = pAL[0];
        *(uint4*)(AsLo + r1c * BP + c1c * 8) = pAL[1];
        *(uint4*)(BsHi + r0c * BP + c0c * 8) = pBH[0];
        *(uint4*)(BsHi + r1c * BP + c1c * 8) = pBH[1];
        *(uint4*)(BsLo + r0c * BP + c0c * 8) = pBL[0];
        *(uint4*)(BsLo + r1c * BP + c1c * 8) = pBL[1];
    };

    fetch(0);
    store_tile(0);
    __syncthreads();

    const int nKt = K / 32;
    for (int kt = 0; kt < nKt; ++kt) {
        const int s = kt & 1;
        if (kt + 1 < nKt) fetch((kt + 1) * 32);

        const __nv_bfloat16* AsHi = smb + s * GST;
        const __nv_bfloat16* AsLo = AsHi + 128 * BP;
        const __nv_bfloat16* BsHi = AsLo + 128 * BP;
        const __nv_bfloat16* BsLo = BsHi + 128 * BP;

#pragma unroll
        for (int ks = 0; ks < 2; ++ks) {
            const int kk = ks * 16;
            unsigned ah[4][4], al[4][4];
#pragma unroll
            for (int mt = 0; mt < 4; ++mt) {
                int m = wm * 64 + mt * 16 + g;
                const __nv_bfloat16* pH = AsHi + m * BP + kk + tig * 2;
                const __nv_bfloat16* pL = AsLo + m * BP + kk + tig * 2;
                ah[mt][0] = *(const unsigned*)(pH);
                ah[mt][1] = *(const unsigned*)(pH + 8 * BP);
                ah[mt][2] = *(const unsigned*)(pH + 8);
                ah[mt][3] = *(const unsigned*)(pH + 8 * BP + 8);
                al[mt][0] = *(const unsigned*)(pL);
                al[mt][1] = *(const unsigned*)(pL + 8 * BP);
                al[mt][2] = *(const unsigned*)(pL + 8);
                al[mt][3] = *(const unsigned*)(pL + 8 * BP + 8);
            }
            unsigned bh[4][2], bl[4][2];
#pragma unroll
            for (int nt = 0; nt < 4; ++nt) {
                int n = wn * 32 + nt * 8 + g;
                const __nv_bfloat16* pH = BsHi + n * BP + kk + tig * 2;
                const __nv_bfloat16* pL = BsLo + n * BP + kk + tig * 2;
                bh[nt][0] = *(const unsigned*)(pH);
                bh[nt][1] = *(const unsigned*)(pH + 8);
                bl[nt][0] = *(const unsigned*)(pL);
                bl[nt][1] = *(const unsigned*)(pL + 8);
            }
            // term-outer sweeps: same-acc reuse distance = 16 mmas
#pragma unroll
            for (int mt = 0; mt < 4; ++mt)
#pragma unroll
                for (int nt = 0; nt < 4; ++nt)
                    mma_bf16(acc[mt][nt], ah[mt][0], ah[mt][1], ah[mt][2], ah[mt][3],
                             bh[nt][0], bh[nt][1]);
#pragma unroll
            for (int mt = 0; mt < 4; ++mt)
#pragma unroll
                for (int nt = 0; nt < 4; ++nt)
                    mma_bf16(acc[mt][nt], al[mt][0], al[mt][1], al[mt][2], al[mt][3],
                             bh[nt][0], bh[nt][1]);
#pragma unroll
            for (int mt = 0; mt < 4; ++mt)
#pragma unroll
                for (int nt = 0; nt < 4; ++nt)
                    mma_bf16(acc[mt][nt], ah[mt][0], ah[mt][1], ah[mt][2], ah[mt][3],
                             bl[nt][0], bl[nt][1]);
        }
        if (kt + 1 < nKt) store_tile(s ^ 1);
        __syncthreads();
    }

#pragma unroll
    for (int mt = 0; mt < 4; ++mt) {
#pragma unroll
        for (int nt = 0; nt < 4; ++nt) {
            int jj = bc * 128 + wn * 32 + nt * 8 + tig * 2;
#pragma unroll
            for (int half = 0; half < 2; ++half) {
                int ii = br * 128 + wm * 64 + mt * 16 + g + half * 8;
                float2 val;
                val.x = acc[mt][nt][half * 2 + 0];
                val.y = acc[mt][nt][half * 2 + 1];
                if (GEMM3 == 0) {
                    *(float2*)(C + (long)ii * N + jj) = val;
                } else {
                    int b = ii >> 9, l = ii & 511;
                    int h = jj >> 6, d = jj & 63;
                    *(float2*)(C + (((long)(b * 16 + h) * 512) + l) * 64 + d) = val;
                }
            }
        }
    }
}

// ====================================================================
// Tensor-core flash attention, all-bf16 3-term.
// R11: S and PV mma loops reordered kc-outer/term-outer (same-acc
// distance 12 consecutive -> 8 independent between reuses).
// ====================================================================
#define KP  72
#define VTP 36
#define PP  36
#define QSP 68
#define OFF_KHI 0
#define OFF_KLO 2304
#define OFF_VTH 4608
#define OFF_VTL 6912
#define OFF_PQ  9216
#define OFF_MS  18432
#define ATTN_SMEM_FLOATS 20480            // 81920 B

template<int OUTBF>
__global__ void __launch_bounds__(256, 1) attn_tc(
    const float* __restrict__ Q,
    const float* __restrict__ Kb, long kBS, long kHS, int kRS,
    const float* __restrict__ Vb, long vBS, long vHS, int vRS,
    const unsigned char* __restrict__ mask8,
    float* __restrict__ Ob, long oBS, long oHS, int oRS,
    int residual)
{
    extern __shared__ float sm[];
    __nv_bfloat16* Khi = (__nv_bfloat16*)(sm + OFF_KHI);
    __nv_bfloat16* Klo = (__nv_bfloat16*)(sm + OFF_KLO);
    unsigned* VtHi = (unsigned*)(sm + OFF_VTH);
    unsigned* VtLo = (unsigned*)(sm + OFF_VTL);
    float*    Qs   = sm + OFF_PQ;
    unsigned* PH   = (unsigned*)(sm + OFF_PQ);
    unsigned* PL   = PH + 128 * PP;
    unsigned char* Ms = (unsigned char*)(sm + OFF_MS);

    const int b  = blockIdx.z;
    const int h  = blockIdx.y;
    const int q0 = blockIdx.x * 128;

    const float* Qp = Q + (((long)(b*16 + h) * 512) + q0) * 64;
    const float* Kp = Kb + (long)b * kBS + (long)h * kHS;
    const float* Vp = Vb + (long)b * vBS + (long)h * vHS;
    const unsigned char* Mp = mask8 + (long)b * LL * LL + (long)q0 * LL;
    float* Op = Ob + (long)b * oBS + (long)h * oHS + (long)q0 * oRS;
    __nv_bfloat16* OHi = (__nv_bfloat16*)g_atthi + (long)b * oBS + (long)h * oHS + (long)q0 * oRS;
    __nv_bfloat16* OLo = (__nv_bfloat16*)g_attlo + (long)b * oBS + (long)h * oHS + (long)q0 * oRS;

    const int tid  = threadIdx.x;
    const int w    = tid >> 5;
    const int lane = tid & 31;
    const int g    = lane >> 2;
    const int tig  = lane & 3;
    const int r0   = w * 16 + g;

#pragma unroll
    for (int it = 0; it < 8; ++it) {
        int f = tid + it * 256;
        int row = f >> 4, c4 = f & 15;
        float4 v = *(const float4*)(Qp + (long)row * 64 + c4 * 4);
        float* dst = Qs + row * QSP + c4 * 4;
        dst[0] = v.x; dst[1] = v.y; dst[2] = v.z; dst[3] = v.w;
    }
    __syncthreads();

    unsigned qh[4][4], ql[4][4];
#pragma unroll
    for (int kc = 0; kc < 4; ++kc) {
        const float* p0 = Qs + (r0)     * QSP + kc * 16 + tig * 2;
        const float* p1 = Qs + (r0 + 8) * QSP + kc * 16 + tig * 2;
        bsplit2(p0[0] * 0.125f, p0[1] * 0.125f, qh[kc][0], ql[kc][0]);
        bsplit2(p1[0] * 0.125f, p1[1] * 0.125f, qh[kc][1], ql[kc][1]);
        bsplit2(p0[8] * 0.125f, p0[9] * 0.125f, qh[kc][2], ql[kc][2]);
        bsplit2(p1[8] * 0.125f, p1[9] * 0.125f, qh[kc][3], ql[kc][3]);
    }

    float oacc[8][4];
#pragma unroll
    for (int nt = 0; nt < 8; ++nt)
#pragma unroll
        for (int i = 0; i < 4; ++i) oacc[nt][i] = 0.f;

    float m0 = -1e30f, m1 = -1e30f, l0 = 0.f, l1 = 0.f;

    for (int kt = 0; kt < 8; ++kt) {
        const int k0 = kt * 64;

#pragma unroll
        for (int it = 0; it < 4; ++it) {
            int f = tid + it * 256;
            int row = f >> 4, c4 = f & 15;
            float4 kv = *(const float4*)(Kp + (long)(k0 + row) * kRS + c4 * 4);
            unsigned h01, l01, h23, l23;
            bsplit2(kv.x, kv.y, h01, l01);
            bsplit2(kv.z, kv.w, h23, l23);
            *(uint2*)(Khi + row * KP + c4 * 4) = make_uint2(h01, h23);
            *(uint2*)(Klo + row * KP + c4 * 4) = make_uint2(l01, l23);
        }
#pragma unroll
        for (int it = 0; it < 2; ++it) {
            int idx = tid + it * 256;
            int jp = idx & 31;
            int c4 = idx >> 5;
            const float* v0 = Vp + (long)(k0 + 2 * jp) * vRS + c4 * 4;
            float4 a = *(const float4*)v0;
            float4 bq = *(const float4*)(v0 + vRS);
            unsigned hh, ll;
            bsplit2(a.x, bq.x, hh, ll);
            VtHi[(c4 * 4 + 0) * VTP + jp] = hh; VtLo[(c4 * 4 + 0) * VTP + jp] = ll;
            bsplit2(a.y, bq.y, hh, ll);
            VtHi[(c4 * 4 + 1) * VTP + jp] = hh; VtLo[(c4 * 4 + 1) * VTP + jp] = ll;
            bsplit2(a.z, bq.z, hh, ll);
            VtHi[(c4 * 4 + 2) * VTP + jp] = hh; VtLo[(c4 * 4 + 2) * VTP + jp] = ll;
            bsplit2(a.w, bq.w, hh, ll);
            VtHi[(c4 * 4 + 3) * VTP + jp] = hh; VtLo[(c4 * 4 + 3) * VTP + jp] = ll;
        }
#pragma unroll
        for (int it = 0; it < 2; ++it) {
            int u = tid + it * 256;
            int row = u >> 2, c16 = u & 3;
            uint4 m = *(const uint4*)(Mp + (long)row * LL + k0 + c16 * 16);
            ((uint4*)Ms)[row * 4 + c16] = m;
        }
        __syncthreads();

        // ---- S = Q K^T : kc-outer, term-outer (indep distance 8) ----
        float sacc[8][4];
#pragma unroll
        for (int nt = 0; nt < 8; ++nt)
#pragma unroll
            for (int i = 0; i < 4; ++i) sacc[nt][i] = 0.f;
#pragma unroll
        for (int kc = 0; kc < 4; ++kc) {
            unsigned bh[8][2], bl[8][2];
#pragma unroll
            for (int nt = 0; nt < 8; ++nt) {
                const __nv_bfloat16* pH = Khi + (nt * 8 + g) * KP + kc * 16 + tig * 2;
                const __nv_bfloat16* pL = Klo + (nt * 8 + g) * KP + kc * 16 + tig * 2;
                bh[nt][0] = *(const unsigned*)(pH);
                bh[nt][1] = *(const unsigned*)(pH + 8);
                bl[nt][0] = *(const unsigned*)(pL);
                bl[nt][1] = *(const unsigned*)(pL + 8);
            }
#pragma unroll
            for (int nt = 0; nt < 8; ++nt)
                mma_bf16(sacc[nt], qh[kc][0], qh[kc][1], qh[kc][2], qh[kc][3],
                         bh[nt][0], bh[nt][1]);
#pragma unroll
            for (int nt = 0; nt < 8; ++nt)
                mma_bf16(sacc[nt], ql[kc][0], ql[kc][1], ql[kc][2], ql[kc][3],
                         bh[nt][0], bh[nt][1]);
#pragma unroll
            for (int nt = 0; nt < 8; ++nt)
                mma_bf16(sacc[nt], qh[kc][0], qh[kc][1], qh[kc][2], qh[kc][3],
                         bl[nt][0], bl[nt][1]);
        }

#pragma unroll
        for (int nt = 0; nt < 8; ++nt) {
            uchar2 mA = *(const uchar2*)(Ms + (r0)     * 64 + nt * 8 + tig * 2);
            uchar2 mB = *(const uchar2*)(Ms + (r0 + 8) * 64 + nt * 8 + tig * 2);
            if (mA.x) sacc[nt][0] = -1e9f;
            if (mA.y) sacc[nt][1] = -1e9f;
            if (mB.x) sacc[nt][2] = -1e9f;
            if (mB.y) sacc[nt][3] = -1e9f;
        }

        float mx0 = -3.0e38f, mx1 = -3.0e38f;
#pragma unroll
        for (int nt = 0; nt < 8; ++nt) {
            mx0 = fmaxf(mx0, fmaxf(sacc[nt][0], sacc[nt][1]));
            mx1 = fmaxf(mx1, fmaxf(sacc[nt][2], sacc[nt][3]));
        }
        mx0 = fmaxf(mx0, __shfl_xor_sync(0xffffffffu, mx0, 1));
        mx0 = fmaxf(mx0, __shfl_xor_sync(0xffffffffu, mx0, 2));
        mx1 = fmaxf(mx1, __shfl_xor_sync(0xffffffffu, mx1, 1));
        mx1 = fmaxf(mx1, __shfl_xor_sync(0xffffffffu, mx1, 2));

        float mn0 = fmaxf(m0, mx0), mn1 = fmaxf(m1, mx1);
        float al0 = __expf(m0 - mn0), al1 = __expf(m1 - mn1);
        m0 = mn0; m1 = mn1;

        float sum0 = 0.f, sum1 = 0.f;
#pragma unroll
        for (int nt = 0; nt < 8; ++nt) {
            float p00 = __expf(sacc[nt][0] - m0);
            float p01 = __expf(sacc[nt][1] - m0);
            float p10 = __expf(sacc[nt][2] - m1);
            float p11 = __expf(sacc[nt][3] - m1);
            sum0 += p00 + p01;
            sum1 += p10 + p11;
            unsigned hh, ll;
            bsplit2(p00, p01, hh, ll);
            PH[(r0)     * PP + nt * 4 + tig] = hh;
            PL[(r0)     * PP + nt * 4 + tig] = ll;
            bsplit2(p10, p11, hh, ll);
            PH[(r0 + 8) * PP + nt * 4 + tig] = hh;
            PL[(r0 + 8) * PP + nt * 4 + tig] = ll;
        }
        sum0 += __shfl_xor_sync(0xffffffffu, sum0, 1);
        sum0 += __shfl_xor_sync(0xffffffffu, sum0, 2);
        sum1 += __shfl_xor_sync(0xffffffffu, sum1, 1);
        sum1 += __shfl_xor_sync(0xffffffffu, sum1, 2);
        l0 = l0 * al0 + sum0;
        l1 = l1 * al1 + sum1;

#pragma unroll
        for (int nt = 0; nt < 8; ++nt) {
            oacc[nt][0] *= al0; oacc[nt][1] *= al0;
            oacc[nt][2] *= al1; oacc[nt][3] *= al1;
        }
        __syncwarp();

        // ---- O += P V : kc-outer, term-outer ----
#pragma unroll
        for (int kc = 0; kc < 4; ++kc) {
            const unsigned* pHr0 = PH + (r0)     * PP + kc * 8 + tig;
            const unsigned* pHr8 = PH + (r0 + 8) * PP + kc * 8 + tig;
            const unsigned* pLr0 = PL + (r0)     * PP + kc * 8 + tig;
            const unsigned* pLr8 = PL + (r0 + 8) * PP + kc * 8 + tig;
            unsigned ph0 = pHr0[0], ph1 = pHr8[0], ph2 = pHr0[4], ph3 = pHr8[4];
            unsigned pl0 = pLr0[0], pl1 = pLr8[0], pl2 = pLr0[4], pl3 = pLr8[4];
            unsigned vh[8][2], vl[8][2];
#pragma unroll
            for (int nt = 0; nt < 8; ++nt) {
                const unsigned* vH = VtHi + (nt * 8 + g) * VTP + kc * 8 + tig;
                const unsigned* vL = VtLo + (nt * 8 + g) * VTP + kc * 8 + tig;
                vh[nt][0] = vH[0]; vh[nt][1] = vH[4];
                vl[nt][0] = vL[0]; vl[nt][1] = vL[4];
            }
#pragma unroll
            for (int nt = 0; nt < 8; ++nt)
                mma_bf16(oacc[nt], ph0, ph1, ph2, ph3, vh[nt][0], vh[nt][1]);
#pragma unroll
            for (int nt = 0; nt < 8; ++nt)
                mma_bf16(oacc[nt], pl0, pl1, pl2, pl3, vh[nt][0], vh[nt][1]);
#pragma unroll
            for (int nt = 0; nt < 8; ++nt)
                mma_bf16(oacc[nt], ph0, ph1, ph2, ph3, vl[nt][0], vl[nt][1]);
        }
        __syncthreads();
    }

    float inv0 = 1.0f / l0, inv1 = 1.0f / l1;
#pragma unroll
    for (int nt = 0; nt < 8; ++nt) {
        int c = nt * 8 + tig * 2;
        float2 v0 = make_float2(oacc[nt][0] * inv0, oacc[nt][1] * inv0);
        float2 v1 = make_float2(oacc[nt][2] * inv1, oacc[nt][3] * inv1);
        if (OUTBF) {
            unsigned hh, ll;
            bsplit2(v0.x, v0.y, hh, ll);
            *(unsigned*)(OHi + (long)(r0) * oRS + c) = hh;
            *(unsigned*)(OLo + (long)(r0) * oRS + c) = ll;
            bsplit2(v1.x, v1.y, hh, ll);
            *(unsigned*)(OHi + (long)(r0 + 8) * oRS + c) = hh;
            *(unsigned*)(OLo + (long)(r0 + 8) * oRS + c) = ll;
        } else {
            if (residual) {
                float2 qres0 = *(const float2*)(Qp + (long)(r0)     * 64 + c);
                float2 qres1 = *(const float2*)(Qp + (long)(r0 + 8) * 64 + c);
                v0.x += qres0.x; v0.y += qres0.y;
                v1.x += qres1.x; v1.y += qres1.y;
            }
            *(float2*)(Op + (long)(r0)     * oRS + c) = v0;
            *(float2*)(Op + (long)(r0 + 8) * oRS + c) = v1;
        }
    }
}

// ====================================================================
extern "C" void kernel_launch(void* const* d_in, const int* in_sizes, int n_in,
                              void* d_out, int out_size)
{
    (void)in_sizes; (void)n_in; (void)out_size;
    const float* v   = (const float*)d_in[0];
    const float* k   = (const float*)d_in[1];
    const float* q   = (const float*)d_in[2];
    const float* img = (const float*)d_in[3];
    const float* Wv  = (const float*)d_in[4];
    const float* Wk  = (const float*)d_in[5];
    const float* Wq  = (const float*)d_in[6];
    const float* Wm  = (const float*)d_in[7];
    const uint4* absm = (const uint4*)d_in[8];
    const uint4* mask = (const uint4*)d_in[9];
    float* out = (float*)d_out;

    float *vh, *kh, *qh, *qn;
    unsigned char *absm8, *mask8;
    cudaGetSymbolAddress((void**)&vh,  g_vh);
    cudaGetSymbolAddress((void**)&kh,  g_kh);
    cudaGetSymbolAddress((void**)&qh,  g_qh);
    cudaGetSymbolAddress((void**)&qn,  g_qn);
    cudaGetSymbolAddress((void**)&absm8, g_absm8);
    cudaGetSymbolAddress((void**)&mask8, g_mask8);

    pack_masks<<<4096, 256>>>(absm, mask, (uchar4*)absm8, (uchar4*)mask8);
    dim3 gi(MROWS * HS / 4 / 256, 3);
    pack_in<<<gi, 256>>>((const float4*)v, (const float4*)k, (const float4*)q);
    dim3 gw(HS * HS / 4 / 256, 4);
    pack_w<<<gw, 256>>>((const float4*)Wv, (const float4*)Wk,
                        (const float4*)Wq, (const float4*)Wm);

    const int gsmem = 2 * GST * (int)sizeof(__nv_bfloat16);   // 81920
    cudaFuncSetAttribute(gemm_pre<0>,
                         cudaFuncAttributeMaxDynamicSharedMemorySize, gsmem);
    cudaFuncSetAttribute(gemm_pre<1>,
                         cudaFuncAttributeMaxDynamicSharedMemorySize, gsmem);

    dim3 g3(HS / 128, MROWS / 128, 3);
    gemm_pre<1><<<g3, 256, gsmem>>>(nullptr, MROWS, HS, HS);

    const int asmem = ATTN_SMEM_FLOATS * (int)sizeof(float);
    cudaFuncSetAttribute(attn_tc<0>,
                         cudaFuncAttributeMaxDynamicSharedMemorySize, asmem);
    cudaFuncSetAttribute(attn_tc<1>,
                         cudaFuncAttributeMaxDynamicSharedMemorySize, asmem);

    dim3 ga(LL / 128, HH, BB);
    attn_tc<0><<<ga, 256, asmem>>>(
        qh,
        img, (long)LL * HS, 64L, HS,
        img, (long)LL * HS, 64L, HS,
        absm8,
        qn,  (long)HH * LL * DD, (long)LL * DD, DD,
        1);
    attn_tc<1><<<ga, 256, asmem>>>(
        qn,
        kh, (long)HH * LL * DD, (long)LL * DD, DD,
        vh, (long)HH * LL * DD, (long)LL * DD, DD,
        mask8,
        nullptr, (long)LL * HS, 64L, HS,
        0);

    dim3 gg(HS / 128, MROWS / 128);
    gemm_pre<0><<<gg, 256, gsmem>>>(out, MROWS, HS, HS);
}

// round 12
// speedup vs baseline: 1.5132x; 1.5132x over previous
#include <cuda_runtime.h>
#include <cuda_bf16.h>

// Problem constants
#define BB 16
#define LL 512
#define HS 1024
#define HH 16
#define DD 64
#define MROWS (BB*LL)        // 8192

// -------------------- scratch (allocation-free) --------------------
__device__ float g_vh[BB*HH*LL*DD];   // [B,H,L,D]
__device__ float g_kh[BB*HH*LL*DD];
__device__ float g_qh[BB*HH*LL*DD];
__device__ float g_qn[BB*HH*LL*DD];   // modulated q
__device__ unsigned char g_absm8[BB*LL*LL];
__device__ unsigned char g_mask8[BB*LL*LL];
__device__ uint4 g_inhi[3L*MROWS*HS/8];
__device__ uint4 g_inlo[3L*MROWS*HS/8];
__device__ uint4 g_whi[4L*HS*HS/8];
__device__ uint4 g_wlo[4L*HS*HS/8];
__device__ uint4 g_atthi[(long)MROWS*HS/8];
__device__ uint4 g_attlo[(long)MROWS*HS/8];

// ------------------ bf16 helpers ------------------
__device__ __forceinline__ unsigned pack2bf(__nv_bfloat16 a, __nv_bfloat16 b) {
    __nv_bfloat162 t; t.x = a; t.y = b;
    return reinterpret_cast<unsigned&>(t);
}

__device__ __forceinline__ void bsplit2(float x0, float x1, unsigned &hi, unsigned &lo) {
    __nv_bfloat16 h0 = __float2bfloat16(x0);
    __nv_bfloat16 h1 = __float2bfloat16(x1);
    __nv_bfloat16 l0 = __float2bfloat16(x0 - __bfloat162float(h0));
    __nv_bfloat16 l1 = __float2bfloat16(x1 - __bfloat162float(h1));
    hi = pack2bf(h0, h1);
    lo = pack2bf(l0, l1);
}

__device__ __forceinline__ void mma_bf16(float d[4],
                                         unsigned a0, unsigned a1, unsigned a2, unsigned a3,
                                         unsigned b0, unsigned b1)
{
    asm volatile(
        "mma.sync.aligned.m16n8k16.row.col.f32.bf16.bf16.f32 "
        "{%0,%1,%2,%3}, {%4,%5,%6,%7}, {%8,%9}, {%0,%1,%2,%3};\n"
        : "+f"(d[0]), "+f"(d[1]), "+f"(d[2]), "+f"(d[3])
        : "r"(a0), "r"(a1), "r"(a2), "r"(a3), "r"(b0), "r"(b1));
}

__device__ __forceinline__ void cp16(void* smem_dst, const void* gmem_src) {
    unsigned s = (unsigned)__cvta_generic_to_shared(smem_dst);
    asm volatile("cp.async.cg.shared.global [%0], [%1], 16;\n"
                 :: "r"(s), "l"(gmem_src) : "memory");
}
#define CP_COMMIT() asm volatile("cp.async.commit_group;\n" ::: "memory")
#define CP_WAIT(n)  asm volatile("cp.async.wait_group %0;\n" :: "n"(n) : "memory")

// ====================================================================
// Prepack kernels
// ====================================================================
__global__ void __launch_bounds__(256) pack_masks(const uint4* __restrict__ a,
                                                  const uint4* __restrict__ b,
                                                  uchar4* __restrict__ oa,
                                                  uchar4* __restrict__ ob)
{
    int i = blockIdx.x * blockDim.x + threadIdx.x;
    uint4 x = a[i];
    oa[i] = make_uchar4(x.x ? 1 : 0, x.y ? 1 : 0, x.z ? 1 : 0, x.w ? 1 : 0);
    uint4 y = b[i];
    ob[i] = make_uchar4(y.x ? 1 : 0, y.y ? 1 : 0, y.z ? 1 : 0, y.w ? 1 : 0);
}

__global__ void __launch_bounds__(256) pack_in(const float4* __restrict__ v,
                                               const float4* __restrict__ k,
                                               const float4* __restrict__ q)
{
    int z = blockIdx.y;
    const float4* src = (z == 0) ? v : (z == 1) ? k : q;
    long i = (long)blockIdx.x * 256 + threadIdx.x;
    float4 x = src[i];
    unsigned h01, l01, h23, l23;
    bsplit2(x.x, x.y, h01, l01);
    bsplit2(x.z, x.w, h23, l23);
    long d = (long)z * (MROWS * (long)HS / 4) + i;
    ((uint2*)g_inhi)[d] = make_uint2(h01, h23);
    ((uint2*)g_inlo)[d] = make_uint2(l01, l23);
}

__global__ void __launch_bounds__(256) pack_w(const float4* __restrict__ w0,
                                              const float4* __restrict__ w1,
                                              const float4* __restrict__ w2,
                                              const float4* __restrict__ w3)
{
    int z = blockIdx.y;
    const float4* src = (z == 0) ? w0 : (z == 1) ? w1 : (z == 2) ? w2 : w3;
    long i = (long)blockIdx.x * 256 + threadIdx.x;
    float4 x = src[i];
    unsigned h01, l01, h23, l23;
    bsplit2(x.x, x.y, h01, l01);
    bsplit2(x.z, x.w, h23, l23);
    long d = (long)z * ((long)HS * HS / 4) + i;
    ((uint2*)g_whi)[d] = make_uint2(h01, h23);
    ((uint2*)g_wlo)[d] = make_uint2(l01, l23);
}

// ====================================================================
// bf16 GEMM, 3-term compensation, pre-split operands.
// R12: 128x256 CTA tile (warp 64x64), cp.async g2s, 2-stage pipeline.
// ====================================================================
#define BP 40                       // bf16 pitch
#define A_SZ (128*BP)               // bf16 per A array
#define B_SZ (256*BP)
#define STG  (2*A_SZ + 2*B_SZ)      // bf16 per stage = 30720 (61440 B)

template<int GEMM3>
__global__ void __launch_bounds__(256, 1) gemm_pre(float* __restrict__ Cout,
                                                   int M, int N, int K)
{
    extern __shared__ float smf[];
    __nv_bfloat16* smb = (__nv_bfloat16*)smf;

    const __nv_bfloat16 *Ahi, *Alo, *Whi, *Wlo;
    float* C;
    if (GEMM3) {
        int z = blockIdx.z;
        Ahi = (const __nv_bfloat16*)g_inhi + (long)z * MROWS * HS;
        Alo = (const __nv_bfloat16*)g_inlo + (long)z * MROWS * HS;
        Whi = (const __nv_bfloat16*)g_whi + (long)z * HS * HS;
        Wlo = (const __nv_bfloat16*)g_wlo + (long)z * HS * HS;
        C   = (z == 0) ? g_vh : (z == 1) ? g_kh : g_qh;
    } else {
        Ahi = (const __nv_bfloat16*)g_atthi;
        Alo = (const __nv_bfloat16*)g_attlo;
        Whi = (const __nv_bfloat16*)g_whi + 3L * HS * HS;
        Wlo = (const __nv_bfloat16*)g_wlo + 3L * HS * HS;
        C   = Cout;
    }

    const int tid  = threadIdx.x;
    const int br   = blockIdx.y;
    const int bc   = blockIdx.x;
    const int wid  = tid >> 5;
    const int lane = tid & 31;
    const int g    = lane >> 2;
    const int tig  = lane & 3;
    const int wm   = wid >> 2;      // 0..1 : 64-row strip
    const int wn   = wid & 3;       // 0..3 : 64-col strip

    const __nv_bfloat16* AbH = Ahi + (long)br * 128 * K;
    const __nv_bfloat16* AbL = Alo + (long)br * 128 * K;
    const __nv_bfloat16* BbH = Whi + (long)bc * 256 * K;
    const __nv_bfloat16* BbL = Wlo + (long)bc * 256 * K;

    float acc[4][8][4];
#pragma unroll
    for (int mt = 0; mt < 4; ++mt)
#pragma unroll
        for (int nt = 0; nt < 8; ++nt)
#pragma unroll
            for (int r = 0; r < 4; ++r) acc[mt][nt][r] = 0.f;

    // cp.async issue for one stage: A 512 chunks x2, B 1024 chunks x2.
    auto issue = [&](int s, int kb) {
        __nv_bfloat16* AsHi = smb + s * STG;
        __nv_bfloat16* AsLo = AsHi + A_SZ;
        __nv_bfloat16* BsHi = AsLo + A_SZ;
        __nv_bfloat16* BsLo = BsHi + B_SZ;
#pragma unroll
        for (int i = 0; i < 2; ++i) {
            int ch = tid + i * 256;          // 0..511
            int row = ch >> 2, seg = ch & 3; // seg: 16B slot (8 bf16)
            long go = (long)row * K + kb + seg * 8;
            int  so = row * BP + seg * 8;
            cp16(AsHi + so, AbH + go);
            cp16(AsLo + so, AbL + go);
        }
#pragma unroll
        for (int i = 0; i < 4; ++i) {
            int ch = tid + i * 256;          // 0..1023
            int row = ch >> 2, seg = ch & 3;
            long go = (long)row * K + kb + seg * 8;
            int  so = row * BP + seg * 8;
            cp16(BsHi + so, BbH + go);
            cp16(BsLo + so, BbL + go);
        }
        CP_COMMIT();
    };

    issue(0, 0);

    const int nKt = K / 32;
    for (int kt = 0; kt < nKt; ++kt) {
        const int s = kt & 1;
        if (kt + 1 < nKt) {
            issue(s ^ 1, (kt + 1) * 32);
            CP_WAIT(1);
        } else {
            CP_WAIT(0);
        }
        __syncthreads();

        const __nv_bfloat16* AsHi = smb + s * STG;
        const __nv_bfloat16* AsLo = AsHi + A_SZ;
        const __nv_bfloat16* BsHi = AsLo + A_SZ;
        const __nv_bfloat16* BsLo = BsHi + B_SZ;

#pragma unroll
        for (int ks = 0; ks < 2; ++ks) {
            const int kk = ks * 16;
            unsigned ah[4][4], al[4][4];
#pragma unroll
            for (int mt = 0; mt < 4; ++mt) {
                int m = wm * 64 + mt * 16 + g;
                const __nv_bfloat16* pH = AsHi + m * BP + kk + tig * 2;
                const __nv_bfloat16* pL = AsLo + m * BP + kk + tig * 2;
                ah[mt][0] = *(const unsigned*)(pH);
                ah[mt][1] = *(const unsigned*)(pH + 8 * BP);
                ah[mt][2] = *(const unsigned*)(pH + 8);
                ah[mt][3] = *(const unsigned*)(pH + 8 * BP + 8);
                al[mt][0] = *(const unsigned*)(pL);
                al[mt][1] = *(const unsigned*)(pL + 8 * BP);
                al[mt][2] = *(const unsigned*)(pL + 8);
                al[mt][3] = *(const unsigned*)(pL + 8 * BP + 8);
            }
#pragma unroll
            for (int nt = 0; nt < 8; ++nt) {
                int n = wn * 64 + nt * 8 + g;
                const __nv_bfloat16* pH = BsHi + n * BP + kk + tig * 2;
                const __nv_bfloat16* pL = BsLo + n * BP + kk + tig * 2;
                unsigned bh0 = *(const unsigned*)(pH);
                unsigned bh1 = *(const unsigned*)(pH + 8);
                unsigned bl0 = *(const unsigned*)(pL);
                unsigned bl1 = *(const unsigned*)(pL + 8);
#pragma unroll
                for (int mt = 0; mt < 4; ++mt) {
                    mma_bf16(acc[mt][nt], ah[mt][0], ah[mt][1], ah[mt][2], ah[mt][3],
                             bh0, bh1);
                    mma_bf16(acc[mt][nt], al[mt][0], al[mt][1], al[mt][2], al[mt][3],
                             bh0, bh1);
                    mma_bf16(acc[mt][nt], ah[mt][0], ah[mt][1], ah[mt][2], ah[mt][3],
                             bl0, bl1);
                }
            }
        }
        __syncthreads();
    }

#pragma unroll
    for (int mt = 0; mt < 4; ++mt) {
#pragma unroll
        for (int nt = 0; nt < 8; ++nt) {
            int jj = bc * 256 + wn * 64 + nt * 8 + tig * 2;
#pragma unroll
            for (int half = 0; half < 2; ++half) {
                int ii = br * 128 + wm * 64 + mt * 16 + g + half * 8;
                float2 val;
                val.x = acc[mt][nt][half * 2 + 0];
                val.y = acc[mt][nt][half * 2 + 1];
                if (GEMM3 == 0) {
                    *(float2*)(C + (long)ii * N + jj) = val;
                } else {
                    int b = ii >> 9, l = ii & 511;
                    int h = jj >> 6, d = jj & 63;
                    *(float2*)(C + (((long)(b * 16 + h) * 512) + l) * 64 + d) = val;
                }
            }
        }
    }
}

// ====================================================================
// Tensor-core flash attention, all-bf16 3-term (R9/R10 config — 254 us).
// OUTBF=0: fp32 out (+residual). OUTBF=1: bf16 hi/lo out (feeds out GEMM).
// ====================================================================
#define KP  72
#define VTP 36
#define PP  36
#define QSP 68
#define OFF_KHI 0
#define OFF_KLO 2304
#define OFF_VTH 4608
#define OFF_VTL 6912
#define OFF_PQ  9216
#define OFF_MS  18432
#define ATTN_SMEM_FLOATS 20480            // 81920 B

template<int OUTBF>
__global__ void __launch_bounds__(256, 1) attn_tc(
    const float* __restrict__ Q,
    const float* __restrict__ Kb, long kBS, long kHS, int kRS,
    const float* __restrict__ Vb, long vBS, long vHS, int vRS,
    const unsigned char* __restrict__ mask8,
    float* __restrict__ Ob, long oBS, long oHS, int oRS,
    int residual)
{
    extern __shared__ float sm[];
    __nv_bfloat16* Khi = (__nv_bfloat16*)(sm + OFF_KHI);
    __nv_bfloat16* Klo = (__nv_bfloat16*)(sm + OFF_KLO);
    unsigned* VtHi = (unsigned*)(sm + OFF_VTH);
    unsigned* VtLo = (unsigned*)(sm + OFF_VTL);
    float*    Qs   = sm + OFF_PQ;
    unsigned* PH   = (unsigned*)(sm + OFF_PQ);
    unsigned* PL   = PH + 128 * PP;
    unsigned char* Ms = (unsigned char*)(sm + OFF_MS);

    const int b  = blockIdx.z;
    const int h  = blockIdx.y;
    const int q0 = blockIdx.x * 128;

    const float* Qp = Q + (((long)(b*16 + h) * 512) + q0) * 64;
    const float* Kp = Kb + (long)b * kBS + (long)h * kHS;
    const float* Vp = Vb + (long)b * vBS + (long)h * vHS;
    const unsigned char* Mp = mask8 + (long)b * LL * LL + (long)q0 * LL;
    float* Op = Ob + (long)b * oBS + (long)h * oHS + (long)q0 * oRS;
    __nv_bfloat16* OHi = (__nv_bfloat16*)g_atthi + (long)b * oBS + (long)h * oHS + (long)q0 * oRS;
    __nv_bfloat16* OLo = (__nv_bfloat16*)g_attlo + (long)b * oBS + (long)h * oHS + (long)q0 * oRS;

    const int tid  = threadIdx.x;
    const int w    = tid >> 5;
    const int lane = tid & 31;
    const int g    = lane >> 2;
    const int tig  = lane & 3;
    const int r0   = w * 16 + g;

#pragma unroll
    for (int it = 0; it < 8; ++it) {
        int f = tid + it * 256;
        int row = f >> 4, c4 = f & 15;
        float4 v = *(const float4*)(Qp + (long)row * 64 + c4 * 4);
        float* dst = Qs + row * QSP + c4 * 4;
        dst[0] = v.x; dst[1] = v.y; dst[2] = v.z; dst[3] = v.w;
    }
    __syncthreads();

    unsigned qh[4][4], ql[4][4];
#pragma unroll
    for (int kc = 0; kc < 4; ++kc) {
        const float* p0 = Qs + (r0)     * QSP + kc * 16 + tig * 2;
        const float* p1 = Qs + (r0 + 8) * QSP + kc * 16 + tig * 2;
        bsplit2(p0[0] * 0.125f, p0[1] * 0.125f, qh[kc][0], ql[kc][0]);
        bsplit2(p1[0] * 0.125f, p1[1] * 0.125f, qh[kc][1], ql[kc][1]);
        bsplit2(p0[8] * 0.125f, p0[9] * 0.125f, qh[kc][2], ql[kc][2]);
        bsplit2(p1[8] * 0.125f, p1[9] * 0.125f, qh[kc][3], ql[kc][3]);
    }

    float oacc[8][4];
#pragma unroll
    for (int nt = 0; nt < 8; ++nt)
#pragma unroll
        for (int i = 0; i < 4; ++i) oacc[nt][i] = 0.f;

    float m0 = -1e30f, m1 = -1e30f, l0 = 0.f, l1 = 0.f;

    for (int kt = 0; kt < 8; ++kt) {
        const int k0 = kt * 64;

#pragma unroll
        for (int it = 0; it < 4; ++it) {
            int f = tid + it * 256;
            int row = f >> 4, c4 = f & 15;
            float4 kv = *(const float4*)(Kp + (long)(k0 + row) * kRS + c4 * 4);
            unsigned h01, l01, h23, l23;
            bsplit2(kv.x, kv.y, h01, l01);
            bsplit2(kv.z, kv.w, h23, l23);
            *(uint2*)(Khi + row * KP + c4 * 4) = make_uint2(h01, h23);
            *(uint2*)(Klo + row * KP + c4 * 4) = make_uint2(l01, l23);
        }
#pragma unroll
        for (int it = 0; it < 2; ++it) {
            int idx = tid + it * 256;
            int jp = idx & 31;
            int c4 = idx >> 5;
            const float* v0 = Vp + (long)(k0 + 2 * jp) * vRS + c4 * 4;
            float4 a = *(const float4*)v0;
            float4 bq = *(const float4*)(v0 + vRS);
            unsigned hh, ll;
            bsplit2(a.x, bq.x, hh, ll);
            VtHi[(c4 * 4 + 0) * VTP + jp] = hh; VtLo[(c4 * 4 + 0) * VTP + jp] = ll;
            bsplit2(a.y, bq.y, hh, ll);
            VtHi[(c4 * 4 + 1) * VTP + jp] = hh; VtLo[(c4 * 4 + 1) * VTP + jp] = ll;
            bsplit2(a.z, bq.z, hh, ll);
            VtHi[(c4 * 4 + 2) * VTP + jp] = hh; VtLo[(c4 * 4 + 2) * VTP + jp] = ll;
            bsplit2(a.w, bq.w, hh, ll);
            VtHi[(c4 * 4 + 3) * VTP + jp] = hh; VtLo[(c4 * 4 + 3) * VTP + jp] = ll;
        }
#pragma unroll
        for (int it = 0; it < 2; ++it) {
            int u = tid + it * 256;
            int row = u >> 2, c16 = u & 3;
            uint4 m = *(const uint4*)(Mp + (long)row * LL + k0 + c16 * 16);
            ((uint4*)Ms)[row * 4 + c16] = m;
        }
        __syncthreads();

        float sacc[8][4];
#pragma unroll
        for (int nt = 0; nt < 8; ++nt) {
#pragma unroll
            for (int i = 0; i < 4; ++i) sacc[nt][i] = 0.f;
#pragma unroll
            for (int kc = 0; kc < 4; ++kc) {
                const __nv_bfloat16* pH = Khi + (nt * 8 + g) * KP + kc * 16 + tig * 2;
                const __nv_bfloat16* pL = Klo + (nt * 8 + g) * KP + kc * 16 + tig * 2;
                unsigned bh0 = *(const unsigned*)(pH);
                unsigned bh1 = *(const unsigned*)(pH + 8);
                unsigned bl0 = *(const unsigned*)(pL);
                unsigned bl1 = *(const unsigned*)(pL + 8);
                mma_bf16(sacc[nt], qh[kc][0], qh[kc][1], qh[kc][2], qh[kc][3], bh0, bh1);
                mma_bf16(sacc[nt], ql[kc][0], ql[kc][1], ql[kc][2], ql[kc][3], bh0, bh1);
                mma_bf16(sacc[nt], qh[kc][0], qh[kc][1], qh[kc][2], qh[kc][3], bl0, bl1);
            }
        }

#pragma unroll
        for (int nt = 0; nt < 8; ++nt) {
            uchar2 mA = *(const uchar2*)(Ms + (r0)     * 64 + nt * 8 + tig * 2);
            uchar2 mB = *(const uchar2*)(Ms + (r0 + 8) * 64 + nt * 8 + tig * 2);
            if (mA.x) sacc[nt][0] = -1e9f;
            if (mA.y) sacc[nt][1] = -1e9f;
            if (mB.x) sacc[nt][2] = -1e9f;
            if (mB.y) sacc[nt][3] = -1e9f;
        }

        float mx0 = -3.0e38f, mx1 = -3.0e38f;
#pragma unroll
        for (int nt = 0; nt < 8; ++nt) {
            mx0 = fmaxf(mx0, fmaxf(sacc[nt][0], sacc[nt][1]));
            mx1 = fmaxf(mx1, fmaxf(sacc[nt][2], sacc[nt][3]));
        }
        mx0 = fmaxf(mx0, __shfl_xor_sync(0xffffffffu, mx0, 1));
        mx0 = fmaxf(mx0, __shfl_xor_sync(0xffffffffu, mx0, 2));
        mx1 = fmaxf(mx1, __shfl_xor_sync(0xffffffffu, mx1, 1));
        mx1 = fmaxf(mx1, __shfl_xor_sync(0xffffffffu, mx1, 2));

        float mn0 = fmaxf(m0, mx0), mn1 = fmaxf(m1, mx1);
        float al0 = __expf(m0 - mn0), al1 = __expf(m1 - mn1);
        m0 = mn0; m1 = mn1;

        float sum0 = 0.f, sum1 = 0.f;
#pragma unroll
        for (int nt = 0; nt < 8; ++nt) {
            float p00 = __expf(sacc[nt][0] - m0);
            float p01 = __expf(sacc[nt][1] - m0);
            float p10 = __expf(sacc[nt][2] - m1);
            float p11 = __expf(sacc[nt][3] - m1);
            sum0 += p00 + p01;
            sum1 += p10 + p11;
            unsigned hh, ll;
            bsplit2(p00, p01, hh, ll);
            PH[(r0)     * PP + nt * 4 + tig] = hh;
            PL[(r0)     * PP + nt * 4 + tig] = ll;
            bsplit2(p10, p11, hh, ll);
            PH[(r0 + 8) * PP + nt * 4 + tig] = hh;
            PL[(r0 + 8) * PP + nt * 4 + tig] = ll;
        }
        sum0 += __shfl_xor_sync(0xffffffffu, sum0, 1);
        sum0 += __shfl_xor_sync(0xffffffffu, sum0, 2);
        sum1 += __shfl_xor_sync(0xffffffffu, sum1, 1);
        sum1 += __shfl_xor_sync(0xffffffffu, sum1, 2);
        l0 = l0 * al0 + sum0;
        l1 = l1 * al1 + sum1;

#pragma unroll
        for (int nt = 0; nt < 8; ++nt) {
            oacc[nt][0] *= al0; oacc[nt][1] *= al0;
            oacc[nt][2] *= al1; oacc[nt][3] *= al1;
        }
        __syncwarp();

#pragma unroll
        for (int kc = 0; kc < 4; ++kc) {
            const unsigned* pHr0 = PH + (r0)     * PP + kc * 8 + tig;
            const unsigned* pHr8 = PH + (r0 + 8) * PP + kc * 8 + tig;
            const unsigned* pLr0 = PL + (r0)     * PP + kc * 8 + tig;
            const unsigned* pLr8 = PL + (r0 + 8) * PP + kc * 8 + tig;
            unsigned ph0 = pHr0[0], ph1 = pHr8[0], ph2 = pHr0[4], ph3 = pHr8[4];
            unsigned pl0 = pLr0[0], pl1 = pLr8[0], pl2 = pLr0[4], pl3 = pLr8[4];
#pragma unroll
            for (int nt = 0; nt < 8; ++nt) {
                const unsigned* vH = VtHi + (nt * 8 + g) * VTP + kc * 8 + tig;
                const unsigned* vL = VtLo + (nt * 8 + g) * VTP + kc * 8 + tig;
                unsigned bh0 = vH[0], bh1 = vH[4];
                unsigned bl0 = vL[0], bl1 = vL[4];
                mma_bf16(oacc[nt], ph0, ph1, ph2, ph3, bh0, bh1);
                mma_bf16(oacc[nt], pl0, pl1, pl2, pl3, bh0, bh1);
                mma_bf16(oacc[nt], ph0, ph1, ph2, ph3, bl0, bl1);
            }
        }
        __syncthreads();
    }

    float inv0 = 1.0f / l0, inv1 = 1.0f / l1;
#pragma unroll
    for (int nt = 0; nt < 8; ++nt) {
        int c = nt * 8 + tig * 2;
        float2 v0 = make_float2(oacc[nt][0] * inv0, oacc[nt][1] * inv0);
        float2 v1 = make_float2(oacc[nt][2] * inv1, oacc[nt][3] * inv1);
        if (OUTBF) {
            unsigned hh, ll;
            bsplit2(v0.x, v0.y, hh, ll);
            *(unsigned*)(OHi + (long)(r0) * oRS + c) = hh;
            *(unsigned*)(OLo + (long)(r0) * oRS + c) = ll;
            bsplit2(v1.x, v1.y, hh, ll);
            *(unsigned*)(OHi + (long)(r0 + 8) * oRS + c) = hh;
            *(unsigned*)(OLo + (long)(r0 + 8) * oRS + c) = ll;
        } else {
            if (residual) {
                float2 qres0 = *(const float2*)(Qp + (long)(r0)     * 64 + c);
                float2 qres1 = *(const float2*)(Qp + (long)(r0 + 8) * 64 + c);
                v0.x += qres0.x; v0.y += qres0.y;
                v1.x += qres1.x; v1.y += qres1.y;
            }
            *(float2*)(Op + (long)(r0)     * oRS + c) = v0;
            *(float2*)(Op + (long)(r0 + 8) * oRS + c) = v1;
        }
    }
}

// ====================================================================
extern "C" void kernel_launch(void* const* d_in, const int* in_sizes, int n_in,
                              void* d_out, int out_size)
{
    (void)in_sizes; (void)n_in; (void)out_size;
    const float* v   = (const float*)d_in[0];
    const float* k   = (const float*)d_in[1];
    const float* q   = (const float*)d_in[2];
    const float* img = (const float*)d_in[3];
    const float* Wv  = (const float*)d_in[4];
    const float* Wk  = (const float*)d_in[5];
    const float* Wq  = (const float*)d_in[6];
    const float* Wm  = (const float*)d_in[7];
    const uint4* absm = (const uint4*)d_in[8];
    const uint4* mask = (const uint4*)d_in[9];
    float* out = (float*)d_out;

    float *vh, *kh, *qh, *qn;
    unsigned char *absm8, *mask8;
    cudaGetSymbolAddress((void**)&vh,  g_vh);
    cudaGetSymbolAddress((void**)&kh,  g_kh);
    cudaGetSymbolAddress((void**)&qh,  g_qh);
    cudaGetSymbolAddress((void**)&qn,  g_qn);
    cudaGetSymbolAddress((void**)&absm8, g_absm8);
    cudaGetSymbolAddress((void**)&mask8, g_mask8);

    pack_masks<<<4096, 256>>>(absm, mask, (uchar4*)absm8, (uchar4*)mask8);
    dim3 gi(MROWS * HS / 4 / 256, 3);
    pack_in<<<gi, 256>>>((const float4*)v, (const float4*)k, (const float4*)q);
    dim3 gw(HS * HS / 4 / 256, 4);
    pack_w<<<gw, 256>>>((const float4*)Wv, (const float4*)Wk,
                        (const float4*)Wq, (const float4*)Wm);

    const int gsmem = 2 * STG * (int)sizeof(__nv_bfloat16);   // 122880
    cudaFuncSetAttribute(gemm_pre<0>,
                         cudaFuncAttributeMaxDynamicSharedMemorySize, gsmem);
    cudaFuncSetAttribute(gemm_pre<1>,
                         cudaFuncAttributeMaxDynamicSharedMemorySize, gsmem);

    dim3 g3(HS / 256, MROWS / 128, 3);   // (4, 64, 3)
    gemm_pre<1><<<g3, 256, gsmem>>>(nullptr, MROWS, HS, HS);

    const int asmem = ATTN_SMEM_FLOATS * (int)sizeof(float);
    cudaFuncSetAttribute(attn_tc<0>,
                         cudaFuncAttributeMaxDynamicSharedMemorySize, asmem);
    cudaFuncSetAttribute(attn_tc<1>,
                         cudaFuncAttributeMaxDynamicSharedMemorySize, asmem);

    dim3 ga(LL / 128, HH, BB);
    attn_tc<0><<<ga, 256, asmem>>>(
        qh,
        img, (long)LL * HS, 64L, HS,
        img, (long)LL * HS, 64L, HS,
        absm8,
        qn,  (long)HH * LL * DD, (long)LL * DD, DD,
        1);
    attn_tc<1><<<ga, 256, asmem>>>(
        qn,
        kh, (long)HH * LL * DD, (long)LL * DD, DD,
        vh, (long)HH * LL * DD, (long)LL * DD, DD,
        mask8,
        nullptr, (long)LL * HS, 64L, HS,
        0);

    dim3 gg(HS / 256, MROWS / 128);   // (4, 64)
    gemm_pre<0><<<gg, 256, gsmem>>>(out, MROWS, HS, HS);
}

// round 13
// speedup vs baseline: 1.5535x; 1.0266x over previous
#include <cuda_runtime.h>
#include <cuda_bf16.h>

// Problem constants
#define BB 16
#define LL 512
#define HS 1024
#define HH 16
#define DD 64
#define MROWS (BB*LL)        // 8192

// -------------------- scratch (allocation-free) --------------------
__device__ float g_vh[BB*HH*LL*DD];   // [B,H,L,D]
__device__ float g_kh[BB*HH*LL*DD];
__device__ float g_qh[BB*HH*LL*DD];
__device__ float g_qn[BB*HH*LL*DD];   // modulated q
__device__ unsigned char g_absm8[BB*LL*LL];
__device__ unsigned char g_mask8[BB*LL*LL];
__device__ uint4 g_inhi[3L*MROWS*HS/8];
__device__ uint4 g_inlo[3L*MROWS*HS/8];
__device__ uint4 g_whi[4L*HS*HS/8];
__device__ uint4 g_wlo[4L*HS*HS/8];
__device__ uint4 g_atthi[(long)MROWS*HS/8];
__device__ uint4 g_attlo[(long)MROWS*HS/8];

// ------------------ bf16 helpers ------------------
__device__ __forceinline__ unsigned pack2bf(__nv_bfloat16 a, __nv_bfloat16 b) {
    __nv_bfloat162 t; t.x = a; t.y = b;
    return reinterpret_cast<unsigned&>(t);
}

__device__ __forceinline__ void bsplit2(float x0, float x1, unsigned &hi, unsigned &lo) {
    __nv_bfloat16 h0 = __float2bfloat16(x0);
    __nv_bfloat16 h1 = __float2bfloat16(x1);
    __nv_bfloat16 l0 = __float2bfloat16(x0 - __bfloat162float(h0));
    __nv_bfloat16 l1 = __float2bfloat16(x1 - __bfloat162float(h1));
    hi = pack2bf(h0, h1);
    lo = pack2bf(l0, l1);
}

__device__ __forceinline__ void mma_bf16(float d[4],
                                         unsigned a0, unsigned a1, unsigned a2, unsigned a3,
                                         unsigned b0, unsigned b1)
{
    asm volatile(
        "mma.sync.aligned.m16n8k16.row.col.f32.bf16.bf16.f32 "
        "{%0,%1,%2,%3}, {%4,%5,%6,%7}, {%8,%9}, {%0,%1,%2,%3};\n"
        : "+f"(d[0]), "+f"(d[1]), "+f"(d[2]), "+f"(d[3])
        : "r"(a0), "r"(a1), "r"(a2), "r"(a3), "r"(b0), "r"(b1));
}

__device__ __forceinline__ void cp16(void* smem_dst, const void* gmem_src) {
    unsigned s = (unsigned)__cvta_generic_to_shared(smem_dst);
    asm volatile("cp.async.cg.shared.global [%0], [%1], 16;\n"
                 :: "r"(s), "l"(gmem_src) : "memory");
}
#define CP_COMMIT() asm volatile("cp.async.commit_group;\n" ::: "memory")
#define CP_WAIT(n)  asm volatile("cp.async.wait_group %0;\n" :: "n"(n) : "memory")

// ====================================================================
// Prepack kernels
// ====================================================================
__global__ void __launch_bounds__(256) pack_masks(const uint4* __restrict__ a,
                                                  const uint4* __restrict__ b,
                                                  uchar4* __restrict__ oa,
                                                  uchar4* __restrict__ ob)
{
    int i = blockIdx.x * blockDim.x + threadIdx.x;
    uint4 x = a[i];
    oa[i] = make_uchar4(x.x ? 1 : 0, x.y ? 1 : 0, x.z ? 1 : 0, x.w ? 1 : 0);
    uint4 y = b[i];
    ob[i] = make_uchar4(y.x ? 1 : 0, y.y ? 1 : 0, y.z ? 1 : 0, y.w ? 1 : 0);
}

__global__ void __launch_bounds__(256) pack_in(const float4* __restrict__ v,
                                               const float4* __restrict__ k,
                                               const float4* __restrict__ q)
{
    int z = blockIdx.y;
    const float4* src = (z == 0) ? v : (z == 1) ? k : q;
    long i = (long)blockIdx.x * 256 + threadIdx.x;
    float4 x = src[i];
    unsigned h01, l01, h23, l23;
    bsplit2(x.x, x.y, h01, l01);
    bsplit2(x.z, x.w, h23, l23);
    long d = (long)z * (MROWS * (long)HS / 4) + i;
    ((uint2*)g_inhi)[d] = make_uint2(h01, h23);
    ((uint2*)g_inlo)[d] = make_uint2(l01, l23);
}

__global__ void __launch_bounds__(256) pack_w(const float4* __restrict__ w0,
                                              const float4* __restrict__ w1,
                                              const float4* __restrict__ w2,
                                              const float4* __restrict__ w3)
{
    int z = blockIdx.y;
    const float4* src = (z == 0) ? w0 : (z == 1) ? w1 : (z == 2) ? w2 : w3;
    long i = (long)blockIdx.x * 256 + threadIdx.x;
    float4 x = src[i];
    unsigned h01, l01, h23, l23;
    bsplit2(x.x, x.y, h01, l01);
    bsplit2(x.z, x.w, h23, l23);
    long d = (long)z * ((long)HS * HS / 4) + i;
    ((uint2*)g_whi)[d] = make_uint2(h01, h23);
    ((uint2*)g_wlo)[d] = make_uint2(l01, l23);
}

// ====================================================================
// bf16 GEMM, 3-term compensation, pre-split operands.
// R13: 128x128 CTA tile, cp.async g2s, 2-stage pipeline,
// __launch_bounds__(256, 2) -> 2 CTAs/SM = 16 warps (HMMA latency hiding).
// ====================================================================
#define BP 40                       // bf16 pitch
#define STG (4*128*BP)              // bf16 per stage = 20480 (40960 B)

template<int GEMM3>
__global__ void __launch_bounds__(256, 2) gemm_pre(float* __restrict__ Cout,
                                                   int M, int N, int K)
{
    extern __shared__ float smf[];
    __nv_bfloat16* smb = (__nv_bfloat16*)smf;

    const __nv_bfloat16 *Ahi, *Alo, *Whi, *Wlo;
    float* C;
    if (GEMM3) {
        int z = blockIdx.z;
        Ahi = (const __nv_bfloat16*)g_inhi + (long)z * MROWS * HS;
        Alo = (const __nv_bfloat16*)g_inlo + (long)z * MROWS * HS;
        Whi = (const __nv_bfloat16*)g_whi + (long)z * HS * HS;
        Wlo = (const __nv_bfloat16*)g_wlo + (long)z * HS * HS;
        C   = (z == 0) ? g_vh : (z == 1) ? g_kh : g_qh;
    } else {
        Ahi = (const __nv_bfloat16*)g_atthi;
        Alo = (const __nv_bfloat16*)g_attlo;
        Whi = (const __nv_bfloat16*)g_whi + 3L * HS * HS;
        Wlo = (const __nv_bfloat16*)g_wlo + 3L * HS * HS;
        C   = Cout;
    }

    const int tid  = threadIdx.x;
    const int br   = blockIdx.y;
    const int bc   = blockIdx.x;
    const int wid  = tid >> 5;
    const int lane = tid & 31;
    const int g    = lane >> 2;
    const int tig  = lane & 3;
    const int wm   = wid >> 2;      // 0..1 : 64-row strip
    const int wn   = wid & 3;       // 0..3 : 32-col strip

    const __nv_bfloat16* AbH = Ahi + (long)br * 128 * K;
    const __nv_bfloat16* AbL = Alo + (long)br * 128 * K;
    const __nv_bfloat16* BbH = Whi + (long)bc * 128 * K;
    const __nv_bfloat16* BbL = Wlo + (long)bc * 128 * K;

    float acc[4][4][4];
#pragma unroll
    for (int mt = 0; mt < 4; ++mt)
#pragma unroll
        for (int nt = 0; nt < 4; ++nt)
#pragma unroll
            for (int r = 0; r < 4; ++r) acc[mt][nt][r] = 0.f;

    // cp.async: 512 16B-chunks per array, 2 per thread per array.
    auto issue = [&](int s, int kb) {
        __nv_bfloat16* AsHi = smb + s * STG;
        __nv_bfloat16* AsLo = AsHi + 128 * BP;
        __nv_bfloat16* BsHi = AsLo + 128 * BP;
        __nv_bfloat16* BsLo = BsHi + 128 * BP;
#pragma unroll
        for (int i = 0; i < 2; ++i) {
            int ch = tid + i * 256;          // 0..511
            int row = ch >> 2, seg = ch & 3;
            long go = (long)row * K + kb + seg * 8;
            int  so = row * BP + seg * 8;
            cp16(AsHi + so, AbH + go);
            cp16(AsLo + so, AbL + go);
            cp16(BsHi + so, BbH + go);
            cp16(BsLo + so, BbL + go);
        }
        CP_COMMIT();
    };

    issue(0, 0);

    const int nKt = K / 32;
    for (int kt = 0; kt < nKt; ++kt) {
        const int s = kt & 1;
        if (kt + 1 < nKt) {
            issue(s ^ 1, (kt + 1) * 32);
            CP_WAIT(1);
        } else {
            CP_WAIT(0);
        }
        __syncthreads();

        const __nv_bfloat16* AsHi = smb + s * STG;
        const __nv_bfloat16* AsLo = AsHi + 128 * BP;
        const __nv_bfloat16* BsHi = AsLo + 128 * BP;
        const __nv_bfloat16* BsLo = BsHi + 128 * BP;

#pragma unroll
        for (int ks = 0; ks < 2; ++ks) {
            const int kk = ks * 16;
            unsigned ah[4][4], al[4][4];
#pragma unroll
            for (int mt = 0; mt < 4; ++mt) {
                int m = wm * 64 + mt * 16 + g;
                const __nv_bfloat16* pH = AsHi + m * BP + kk + tig * 2;
                const __nv_bfloat16* pL = AsLo + m * BP + kk + tig * 2;
                ah[mt][0] = *(const unsigned*)(pH);
                ah[mt][1] = *(const unsigned*)(pH + 8 * BP);
                ah[mt][2] = *(const unsigned*)(pH + 8);
                ah[mt][3] = *(const unsigned*)(pH + 8 * BP + 8);
                al[mt][0] = *(const unsigned*)(pL);
                al[mt][1] = *(const unsigned*)(pL + 8 * BP);
                al[mt][2] = *(const unsigned*)(pL + 8);
                al[mt][3] = *(const unsigned*)(pL + 8 * BP + 8);
            }
#pragma unroll
            for (int nt = 0; nt < 4; ++nt) {
                int n = wn * 32 + nt * 8 + g;
                const __nv_bfloat16* pH = BsHi + n * BP + kk + tig * 2;
                const __nv_bfloat16* pL = BsLo + n * BP + kk + tig * 2;
                unsigned bh0 = *(const unsigned*)(pH);
                unsigned bh1 = *(const unsigned*)(pH + 8);
                unsigned bl0 = *(const unsigned*)(pL);
                unsigned bl1 = *(const unsigned*)(pL + 8);
#pragma unroll
                for (int mt = 0; mt < 4; ++mt) {
                    mma_bf16(acc[mt][nt], ah[mt][0], ah[mt][1], ah[mt][2], ah[mt][3],
                             bh0, bh1);
                    mma_bf16(acc[mt][nt], al[mt][0], al[mt][1], al[mt][2], al[mt][3],
                             bh0, bh1);
                    mma_bf16(acc[mt][nt], ah[mt][0], ah[mt][1], ah[mt][2], ah[mt][3],
                             bl0, bl1);
                }
            }
        }
        __syncthreads();
    }

#pragma unroll
    for (int mt = 0; mt < 4; ++mt) {
#pragma unroll
        for (int nt = 0; nt < 4; ++nt) {
            int jj = bc * 128 + wn * 32 + nt * 8 + tig * 2;
#pragma unroll
            for (int half = 0; half < 2; ++half) {
                int ii = br * 128 + wm * 64 + mt * 16 + g + half * 8;
                float2 val;
                val.x = acc[mt][nt][half * 2 + 0];
                val.y = acc[mt][nt][half * 2 + 1];
                if (GEMM3 == 0) {
                    *(float2*)(C + (long)ii * N + jj) = val;
                } else {
                    int b = ii >> 9, l = ii & 511;
                    int h = jj >> 6, d = jj & 63;
                    *(float2*)(C + (((long)(b * 16 + h) * 512) + l) * 64 + d) = val;
                }
            }
        }
    }
}

// ====================================================================
// Tensor-core flash attention, all-bf16 3-term (R9/R10 config — 254 us).
// OUTBF=0: fp32 out (+residual). OUTBF=1: bf16 hi/lo out (feeds out GEMM).
// ====================================================================
#define KP  72
#define VTP 36
#define PP  36
#define QSP 68
#define OFF_KHI 0
#define OFF_KLO 2304
#define OFF_VTH 4608
#define OFF_VTL 6912
#define OFF_PQ  9216
#define OFF_MS  18432
#define ATTN_SMEM_FLOATS 20480            // 81920 B

template<int OUTBF>
__global__ void __launch_bounds__(256, 1) attn_tc(
    const float* __restrict__ Q,
    const float* __restrict__ Kb, long kBS, long kHS, int kRS,
    const float* __restrict__ Vb, long vBS, long vHS, int vRS,
    const unsigned char* __restrict__ mask8,
    float* __restrict__ Ob, long oBS, long oHS, int oRS,
    int residual)
{
    extern __shared__ float sm[];
    __nv_bfloat16* Khi = (__nv_bfloat16*)(sm + OFF_KHI);
    __nv_bfloat16* Klo = (__nv_bfloat16*)(sm + OFF_KLO);
    unsigned* VtHi = (unsigned*)(sm + OFF_VTH);
    unsigned* VtLo = (unsigned*)(sm + OFF_VTL);
    float*    Qs   = sm + OFF_PQ;
    unsigned* PH   = (unsigned*)(sm + OFF_PQ);
    unsigned* PL   = PH + 128 * PP;
    unsigned char* Ms = (unsigned char*)(sm + OFF_MS);

    const int b  = blockIdx.z;
    const int h  = blockIdx.y;
    const int q0 = blockIdx.x * 128;

    const float* Qp = Q + (((long)(b*16 + h) * 512) + q0) * 64;
    const float* Kp = Kb + (long)b * kBS + (long)h * kHS;
    const float* Vp = Vb + (long)b * vBS + (long)h * vHS;
    const unsigned char* Mp = mask8 + (long)b * LL * LL + (long)q0 * LL;
    float* Op = Ob + (long)b * oBS + (long)h * oHS + (long)q0 * oRS;
    __nv_bfloat16* OHi = (__nv_bfloat16*)g_atthi + (long)b * oBS + (long)h * oHS + (long)q0 * oRS;
    __nv_bfloat16* OLo = (__nv_bfloat16*)g_attlo + (long)b * oBS + (long)h * oHS + (long)q0 * oRS;

    const int tid  = threadIdx.x;
    const int w    = tid >> 5;
    const int lane = tid & 31;
    const int g    = lane >> 2;
    const int tig  = lane & 3;
    const int r0   = w * 16 + g;

#pragma unroll
    for (int it = 0; it < 8; ++it) {
        int f = tid + it * 256;
        int row = f >> 4, c4 = f & 15;
        float4 v = *(const float4*)(Qp + (long)row * 64 + c4 * 4);
        float* dst = Qs + row * QSP + c4 * 4;
        dst[0] = v.x; dst[1] = v.y; dst[2] = v.z; dst[3] = v.w;
    }
    __syncthreads();

    unsigned qh[4][4], ql[4][4];
#pragma unroll
    for (int kc = 0; kc < 4; ++kc) {
        const float* p0 = Qs + (r0)     * QSP + kc * 16 + tig * 2;
        const float* p1 = Qs + (r0 + 8) * QSP + kc * 16 + tig * 2;
        bsplit2(p0[0] * 0.125f, p0[1] * 0.125f, qh[kc][0], ql[kc][0]);
        bsplit2(p1[0] * 0.125f, p1[1] * 0.125f, qh[kc][1], ql[kc][1]);
        bsplit2(p0[8] * 0.125f, p0[9] * 0.125f, qh[kc][2], ql[kc][2]);
        bsplit2(p1[8] * 0.125f, p1[9] * 0.125f, qh[kc][3], ql[kc][3]);
    }

    float oacc[8][4];
#pragma unroll
    for (int nt = 0; nt < 8; ++nt)
#pragma unroll
        for (int i = 0; i < 4; ++i) oacc[nt][i] = 0.f;

    float m0 = -1e30f, m1 = -1e30f, l0 = 0.f, l1 = 0.f;

    for (int kt = 0; kt < 8; ++kt) {
        const int k0 = kt * 64;

#pragma unroll
        for (int it = 0; it < 4; ++it) {
            int f = tid + it * 256;
            int row = f >> 4, c4 = f & 15;
            float4 kv = *(const float4*)(Kp + (long)(k0 + row) * kRS + c4 * 4);
            unsigned h01, l01, h23, l23;
            bsplit2(kv.x, kv.y, h01, l01);
            bsplit2(kv.z, kv.w, h23, l23);
            *(uint2*)(Khi + row * KP + c4 * 4) = make_uint2(h01, h23);
            *(uint2*)(Klo + row * KP + c4 * 4) = make_uint2(l01, l23);
        }
#pragma unroll
        for (int it = 0; it < 2; ++it) {
            int idx = tid + it * 256;
            int jp = idx & 31;
            int c4 = idx >> 5;
            const float* v0 = Vp + (long)(k0 + 2 * jp) * vRS + c4 * 4;
            float4 a = *(const float4*)v0;
            float4 bq = *(const float4*)(v0 + vRS);
            unsigned hh, ll;
            bsplit2(a.x, bq.x, hh, ll);
            VtHi[(c4 * 4 + 0) * VTP + jp] = hh; VtLo[(c4 * 4 + 0) * VTP + jp] = ll;
            bsplit2(a.y, bq.y, hh, ll);
            VtHi[(c4 * 4 + 1) * VTP + jp] = hh; VtLo[(c4 * 4 + 1) * VTP + jp] = ll;
            bsplit2(a.z, bq.z, hh, ll);
            VtHi[(c4 * 4 + 2) * VTP + jp] = hh; VtLo[(c4 * 4 + 2) * VTP + jp] = ll;
            bsplit2(a.w, bq.w, hh, ll);
            VtHi[(c4 * 4 + 3) * VTP + jp] = hh; VtLo[(c4 * 4 + 3) * VTP + jp] = ll;
        }
#pragma unroll
        for (int it = 0; it < 2; ++it) {
            int u = tid + it * 256;
            int row = u >> 2, c16 = u & 3;
            uint4 m = *(const uint4*)(Mp + (long)row * LL + k0 + c16 * 16);
            ((uint4*)Ms)[row * 4 + c16] = m;
        }
        __syncthreads();

        float sacc[8][4];
#pragma unroll
        for (int nt = 0; nt < 8; ++nt) {
#pragma unroll
            for (int i = 0; i < 4; ++i) sacc[nt][i] = 0.f;
#pragma unroll
            for (int kc = 0; kc < 4; ++kc) {
                const __nv_bfloat16* pH = Khi + (nt * 8 + g) * KP + kc * 16 + tig * 2;
                const __nv_bfloat16* pL = Klo + (nt * 8 + g) * KP + kc * 16 + tig * 2;
                unsigned bh0 = *(const unsigned*)(pH);
                unsigned bh1 = *(const unsigned*)(pH + 8);
                unsigned bl0 = *(const unsigned*)(pL);
                unsigned bl1 = *(const unsigned*)(pL + 8);
                mma_bf16(sacc[nt], qh[kc][0], qh[kc][1], qh[kc][2], qh[kc][3], bh0, bh1);
                mma_bf16(sacc[nt], ql[kc][0], ql[kc][1], ql[kc][2], ql[kc][3], bh0, bh1);
                mma_bf16(sacc[nt], qh[kc][0], qh[kc][1], qh[kc][2], qh[kc][3], bl0, bl1);
            }
        }

#pragma unroll
        for (int nt = 0; nt < 8; ++nt) {
            uchar2 mA = *(const uchar2*)(Ms + (r0)     * 64 + nt * 8 + tig * 2);
            uchar2 mB = *(const uchar2*)(Ms + (r0 + 8) * 64 + nt * 8 + tig * 2);
            if (mA.x) sacc[nt][0] = -1e9f;
            if (mA.y) sacc[nt][1] = -1e9f;
            if (mB.x) sacc[nt][2] = -1e9f;
            if (mB.y) sacc[nt][3] = -1e9f;
        }

        float mx0 = -3.0e38f, mx1 = -3.0e38f;
#pragma unroll
        for (int nt = 0; nt < 8; ++nt) {
            mx0 = fmaxf(mx0, fmaxf(sacc[nt][0], sacc[nt][1]));
            mx1 = fmaxf(mx1, fmaxf(sacc[nt][2], sacc[nt][3]));
        }
        mx0 = fmaxf(mx0, __shfl_xor_sync(0xffffffffu, mx0, 1));
        mx0 = fmaxf(mx0, __shfl_xor_sync(0xffffffffu, mx0, 2));
        mx1 = fmaxf(mx1, __shfl_xor_sync(0xffffffffu, mx1, 1));
        mx1 = fmaxf(mx1, __shfl_xor_sync(0xffffffffu, mx1, 2));

        float mn0 = fmaxf(m0, mx0), mn1 = fmaxf(m1, mx1);
        float al0 = __expf(m0 - mn0), al1 = __expf(m1 - mn1);
        m0 = mn0; m1 = mn1;

        float sum0 = 0.f, sum1 = 0.f;
#pragma unroll
        for (int nt = 0; nt < 8; ++nt) {
            float p00 = __expf(sacc[nt][0] - m0);
            float p01 = __expf(sacc[nt][1] - m0);
            float p10 = __expf(sacc[nt][2] - m1);
            float p11 = __expf(sacc[nt][3] - m1);
            sum0 += p00 + p01;
            sum1 += p10 + p11;
            unsigned hh, ll;
            bsplit2(p00, p01, hh, ll);
            PH[(r0)     * PP + nt * 4 + tig] = hh;
            PL[(r0)     * PP + nt * 4 + tig] = ll;
            bsplit2(p10, p11, hh, ll);
            PH[(r0 + 8) * PP + nt * 4 + tig] = hh;
            PL[(r0 + 8) * PP + nt * 4 + tig] = ll;
        }
        sum0 += __shfl_xor_sync(0xffffffffu, sum0, 1);
        sum0 += __shfl_xor_sync(0xffffffffu, sum0, 2);
        sum1 += __shfl_xor_sync(0xffffffffu, sum1, 1);
        sum1 += __shfl_xor_sync(0xffffffffu, sum1, 2);
        l0 = l0 * al0 + sum0;
        l1 = l1 * al1 + sum1;

#pragma unroll
        for (int nt = 0; nt < 8; ++nt) {
            oacc[nt][0] *= al0; oacc[nt][1] *= al0;
            oacc[nt][2] *= al1; oacc[nt][3] *= al1;
        }
        __syncwarp();

#pragma unroll
        for (int kc = 0; kc < 4; ++kc) {
            const unsigned* pHr0 = PH + (r0)     * PP + kc * 8 + tig;
            const unsigned* pHr8 = PH + (r0 + 8) * PP + kc * 8 + tig;
            const unsigned* pLr0 = PL + (r0)     * PP + kc * 8 + tig;
            const unsigned* pLr8 = PL + (r0 + 8) * PP + kc * 8 + tig;
            unsigned ph0 = pHr0[0], ph1 = pHr8[0], ph2 = pHr0[4], ph3 = pHr8[4];
            unsigned pl0 = pLr0[0], pl1 = pLr8[0], pl2 = pLr0[4], pl3 = pLr8[4];
#pragma unroll
            for (int nt = 0; nt < 8; ++nt) {
                const unsigned* vH = VtHi + (nt * 8 + g) * VTP + kc * 8 + tig;
                const unsigned* vL = VtLo + (nt * 8 + g) * VTP + kc * 8 + tig;
                unsigned bh0 = vH[0], bh1 = vH[4];
                unsigned bl0 = vL[0], bl1 = vL[4];
                mma_bf16(oacc[nt], ph0, ph1, ph2, ph3, bh0, bh1);
                mma_bf16(oacc[nt], pl0, pl1, pl2, pl3, bh0, bh1);
                mma_bf16(oacc[nt], ph0, ph1, ph2, ph3, bl0, bl1);
            }
        }
        __syncthreads();
    }

    float inv0 = 1.0f / l0, inv1 = 1.0f / l1;
#pragma unroll
    for (int nt = 0; nt < 8; ++nt) {
        int c = nt * 8 + tig * 2;
        float2 v0 = make_float2(oacc[nt][0] * inv0, oacc[nt][1] * inv0);
        float2 v1 = make_float2(oacc[nt][2] * inv1, oacc[nt][3] * inv1);
        if (OUTBF) {
            unsigned hh, ll;
            bsplit2(v0.x, v0.y, hh, ll);
            *(unsigned*)(OHi + (long)(r0) * oRS + c) = hh;
            *(unsigned*)(OLo + (long)(r0) * oRS + c) = ll;
            bsplit2(v1.x, v1.y, hh, ll);
            *(unsigned*)(OHi + (long)(r0 + 8) * oRS + c) = hh;
            *(unsigned*)(OLo + (long)(r0 + 8) * oRS + c) = ll;
        } else {
            if (residual) {
                float2 qres0 = *(const float2*)(Qp + (long)(r0)     * 64 + c);
                float2 qres1 = *(const float2*)(Qp + (long)(r0 + 8) * 64 + c);
                v0.x += qres0.x; v0.y += qres0.y;
                v1.x += qres1.x; v1.y += qres1.y;
            }
            *(float2*)(Op + (long)(r0)     * oRS + c) = v0;
            *(float2*)(Op + (long)(r0 + 8) * oRS + c) = v1;
        }
    }
}

// ====================================================================
extern "C" void kernel_launch(void* const* d_in, const int* in_sizes, int n_in,
                              void* d_out, int out_size)
{
    (void)in_sizes; (void)n_in; (void)out_size;
    const float* v   = (const float*)d_in[0];
    const float* k   = (const float*)d_in[1];
    const float* q   = (const float*)d_in[2];
    const float* img = (const float*)d_in[3];
    const float* Wv  = (const float*)d_in[4];
    const float* Wk  = (const float*)d_in[5];
    const float* Wq  = (const float*)d_in[6];
    const float* Wm  = (const float*)d_in[7];
    const uint4* absm = (const uint4*)d_in[8];
    const uint4* mask = (const uint4*)d_in[9];
    float* out = (float*)d_out;

    float *vh, *kh, *qh, *qn;
    unsigned char *absm8, *mask8;
    cudaGetSymbolAddress((void**)&vh,  g_vh);
    cudaGetSymbolAddress((void**)&kh,  g_kh);
    cudaGetSymbolAddress((void**)&qh,  g_qh);
    cudaGetSymbolAddress((void**)&qn,  g_qn);
    cudaGetSymbolAddress((void**)&absm8, g_absm8);
    cudaGetSymbolAddress((void**)&mask8, g_mask8);

    pack_masks<<<4096, 256>>>(absm, mask, (uchar4*)absm8, (uchar4*)mask8);
    dim3 gi(MROWS * HS / 4 / 256, 3);
    pack_in<<<gi, 256>>>((const float4*)v, (const float4*)k, (const float4*)q);
    dim3 gw(HS * HS / 4 / 256, 4);
    pack_w<<<gw, 256>>>((const float4*)Wv, (const float4*)Wk,
                        (const float4*)Wq, (const float4*)Wm);

    const int gsmem = 2 * STG * (int)sizeof(__nv_bfloat16);   // 81920
    cudaFuncSetAttribute(gemm_pre<0>,
                         cudaFuncAttributeMaxDynamicSharedMemorySize, gsmem);
    cudaFuncSetAttribute(gemm_pre<1>,
                         cudaFuncAttributeMaxDynamicSharedMemorySize, gsmem);

    dim3 g3(HS / 128, MROWS / 128, 3);   // (8, 64, 3)
    gemm_pre<1><<<g3, 256, gsmem>>>(nullptr, MROWS, HS, HS);

    const int asmem = ATTN_SMEM_FLOATS * (int)sizeof(float);
    cudaFuncSetAttribute(attn_tc<0>,
                         cudaFuncAttributeMaxDynamicSharedMemorySize, asmem);
    cudaFuncSetAttribute(attn_tc<1>,
                         cudaFuncAttributeMaxDynamicSharedMemorySize, asmem);

    dim3 ga(LL / 128, HH, BB);
    attn_tc<0><<<ga, 256, asmem>>>(
        qh,
        img, (long)LL * HS, 64L, HS,
        img, (long)LL * HS, 64L, HS,
        absm8,
        qn,  (long)HH * LL * DD, (long)LL * DD, DD,
        1);
    attn_tc<1><<<ga, 256, asmem>>>(
        qn,
        kh, (long)HH * LL * DD, (long)LL * DD, DD,
        vh, (long)HH * LL * DD, (long)LL * DD, DD,
        mask8,
        nullptr, (long)LL * HS, 64L, HS,
        0);

    dim3 gg(HS / 128, MROWS / 128);   // (8, 64)
    gemm_pre<0><<<gg, 256, gsmem>>>(out, MROWS, HS, HS);
}

// round 14
// speedup vs baseline: 1.6153x; 1.0398x over previous
#include <cuda_runtime.h>
#include <cuda_bf16.h>

// Problem constants
#define BB 16
#define LL 512
#define HS 1024
#define HH 16
#define DD 64
#define MROWS (BB*LL)        // 8192

// -------------------- scratch (allocation-free) --------------------
__device__ float g_vh[BB*HH*LL*DD];   // [B,H,L,D]
__device__ float g_kh[BB*HH*LL*DD];
__device__ float g_qh[BB*HH*LL*DD];
__device__ float g_qn[BB*HH*LL*DD];   // modulated q
__device__ unsigned char g_absm8[BB*LL*LL];
__device__ unsigned char g_mask8[BB*LL*LL];
__device__ uint4 g_inhi[3L*MROWS*HS/8];
__device__ uint4 g_inlo[3L*MROWS*HS/8];
__device__ uint4 g_whi[4L*HS*HS/8];
__device__ uint4 g_wlo[4L*HS*HS/8];
__device__ uint4 g_atthi[(long)MROWS*HS/8];
__device__ uint4 g_attlo[(long)MROWS*HS/8];

// ------------------ bf16 helpers ------------------
__device__ __forceinline__ unsigned pack2bf(__nv_bfloat16 a, __nv_bfloat16 b) {
    __nv_bfloat162 t; t.x = a; t.y = b;
    return reinterpret_cast<unsigned&>(t);
}

__device__ __forceinline__ void bsplit2(float x0, float x1, unsigned &hi, unsigned &lo) {
    __nv_bfloat16 h0 = __float2bfloat16(x0);
    __nv_bfloat16 h1 = __float2bfloat16(x1);
    __nv_bfloat16 l0 = __float2bfloat16(x0 - __bfloat162float(h0));
    __nv_bfloat16 l1 = __float2bfloat16(x1 - __bfloat162float(h1));
    hi = pack2bf(h0, h1);
    lo = pack2bf(l0, l1);
}

__device__ __forceinline__ void mma_bf16(float d[4],
                                         unsigned a0, unsigned a1, unsigned a2, unsigned a3,
                                         unsigned b0, unsigned b1)
{
    asm volatile(
        "mma.sync.aligned.m16n8k16.row.col.f32.bf16.bf16.f32 "
        "{%0,%1,%2,%3}, {%4,%5,%6,%7}, {%8,%9}, {%0,%1,%2,%3};\n"
        : "+f"(d[0]), "+f"(d[1]), "+f"(d[2]), "+f"(d[3])
        : "r"(a0), "r"(a1), "r"(a2), "r"(a3), "r"(b0), "r"(b1));
}

__device__ __forceinline__ void cp16(void* smem_dst, const void* gmem_src) {
    unsigned s = (unsigned)__cvta_generic_to_shared(smem_dst);
    asm volatile("cp.async.cg.shared.global [%0], [%1], 16;\n"
                 :: "r"(s), "l"(gmem_src) : "memory");
}
#define CP_COMMIT() asm volatile("cp.async.commit_group;\n" ::: "memory")
#define CP_WAIT(n)  asm volatile("cp.async.wait_group %0;\n" :: "n"(n) : "memory")

// ====================================================================
// Prepack kernels
// ====================================================================
__global__ void __launch_bounds__(256) pack_masks(const uint4* __restrict__ a,
                                                  const uint4* __restrict__ b,
                                                  uchar4* __restrict__ oa,
                                                  uchar4* __restrict__ ob)
{
    int i = blockIdx.x * blockDim.x + threadIdx.x;
    uint4 x = a[i];
    oa[i] = make_uchar4(x.x ? 1 : 0, x.y ? 1 : 0, x.z ? 1 : 0, x.w ? 1 : 0);
    uint4 y = b[i];
    ob[i] = make_uchar4(y.x ? 1 : 0, y.y ? 1 : 0, y.z ? 1 : 0, y.w ? 1 : 0);
}

__global__ void __launch_bounds__(256) pack_in(const float4* __restrict__ v,
                                               const float4* __restrict__ k,
                                               const float4* __restrict__ q)
{
    int z = blockIdx.y;
    const float4* src = (z == 0) ? v : (z == 1) ? k : q;
    long i = (long)blockIdx.x * 256 + threadIdx.x;
    float4 x = src[i];
    unsigned h01, l01, h23, l23;
    bsplit2(x.x, x.y, h01, l01);
    bsplit2(x.z, x.w, h23, l23);
    long d = (long)z * (MROWS * (long)HS / 4) + i;
    ((uint2*)g_inhi)[d] = make_uint2(h01, h23);
    ((uint2*)g_inlo)[d] = make_uint2(l01, l23);
}

__global__ void __launch_bounds__(256) pack_w(const float4* __restrict__ w0,
                                              const float4* __restrict__ w1,
                                              const float4* __restrict__ w2,
                                              const float4* __restrict__ w3)
{
    int z = blockIdx.y;
    const float4* src = (z == 0) ? w0 : (z == 1) ? w1 : (z == 2) ? w2 : w3;
    long i = (long)blockIdx.x * 256 + threadIdx.x;
    float4 x = src[i];
    unsigned h01, l01, h23, l23;
    bsplit2(x.x, x.y, h01, l01);
    bsplit2(x.z, x.w, h23, l23);
    long d = (long)z * ((long)HS * HS / 4) + i;
    ((uint2*)g_whi)[d] = make_uint2(h01, h23);
    ((uint2*)g_wlo)[d] = make_uint2(l01, l23);
}

// ====================================================================
// bf16 GEMM, 3-term compensation, pre-split operands.
// R13 config (best GEMM): 128x128 tile, cp.async, 2 CTAs/SM.
// ====================================================================
#define BP 40                       // bf16 pitch
#define STG (4*128*BP)              // bf16 per stage = 20480 (40960 B)

template<int GEMM3>
__global__ void __launch_bounds__(256, 2) gemm_pre(float* __restrict__ Cout,
                                                   int M, int N, int K)
{
    extern __shared__ float smf[];
    __nv_bfloat16* smb = (__nv_bfloat16*)smf;

    const __nv_bfloat16 *Ahi, *Alo, *Whi, *Wlo;
    float* C;
    if (GEMM3) {
        int z = blockIdx.z;
        Ahi = (const __nv_bfloat16*)g_inhi + (long)z * MROWS * HS;
        Alo = (const __nv_bfloat16*)g_inlo + (long)z * MROWS * HS;
        Whi = (const __nv_bfloat16*)g_whi + (long)z * HS * HS;
        Wlo = (const __nv_bfloat16*)g_wlo + (long)z * HS * HS;
        C   = (z == 0) ? g_vh : (z == 1) ? g_kh : g_qh;
    } else {
        Ahi = (const __nv_bfloat16*)g_atthi;
        Alo = (const __nv_bfloat16*)g_attlo;
        Whi = (const __nv_bfloat16*)g_whi + 3L * HS * HS;
        Wlo = (const __nv_bfloat16*)g_wlo + 3L * HS * HS;
        C   = Cout;
    }

    const int tid  = threadIdx.x;
    const int br   = blockIdx.y;
    const int bc   = blockIdx.x;
    const int wid  = tid >> 5;
    const int lane = tid & 31;
    const int g    = lane >> 2;
    const int tig  = lane & 3;
    const int wm   = wid >> 2;
    const int wn   = wid & 3;

    const __nv_bfloat16* AbH = Ahi + (long)br * 128 * K;
    const __nv_bfloat16* AbL = Alo + (long)br * 128 * K;
    const __nv_bfloat16* BbH = Whi + (long)bc * 128 * K;
    const __nv_bfloat16* BbL = Wlo + (long)bc * 128 * K;

    float acc[4][4][4];
#pragma unroll
    for (int mt = 0; mt < 4; ++mt)
#pragma unroll
        for (int nt = 0; nt < 4; ++nt)
#pragma unroll
            for (int r = 0; r < 4; ++r) acc[mt][nt][r] = 0.f;

    auto issue = [&](int s, int kb) {
        __nv_bfloat16* AsHi = smb + s * STG;
        __nv_bfloat16* AsLo = AsHi + 128 * BP;
        __nv_bfloat16* BsHi = AsLo + 128 * BP;
        __nv_bfloat16* BsLo = BsHi + 128 * BP;
#pragma unroll
        for (int i = 0; i < 2; ++i) {
            int ch = tid + i * 256;
            int row = ch >> 2, seg = ch & 3;
            long go = (long)row * K + kb + seg * 8;
            int  so = row * BP + seg * 8;
            cp16(AsHi + so, AbH + go);
            cp16(AsLo + so, AbL + go);
            cp16(BsHi + so, BbH + go);
            cp16(BsLo + so, BbL + go);
        }
        CP_COMMIT();
    };

    issue(0, 0);

    const int nKt = K / 32;
    for (int kt = 0; kt < nKt; ++kt) {
        const int s = kt & 1;
        if (kt + 1 < nKt) {
            issue(s ^ 1, (kt + 1) * 32);
            CP_WAIT(1);
        } else {
            CP_WAIT(0);
        }
        __syncthreads();

        const __nv_bfloat16* AsHi = smb + s * STG;
        const __nv_bfloat16* AsLo = AsHi + 128 * BP;
        const __nv_bfloat16* BsHi = AsLo + 128 * BP;
        const __nv_bfloat16* BsLo = BsHi + 128 * BP;

#pragma unroll
        for (int ks = 0; ks < 2; ++ks) {
            const int kk = ks * 16;
            unsigned ah[4][4], al[4][4];
#pragma unroll
            for (int mt = 0; mt < 4; ++mt) {
                int m = wm * 64 + mt * 16 + g;
                const __nv_bfloat16* pH = AsHi + m * BP + kk + tig * 2;
                const __nv_bfloat16* pL = AsLo + m * BP + kk + tig * 2;
                ah[mt][0] = *(const unsigned*)(pH);
                ah[mt][1] = *(const unsigned*)(pH + 8 * BP);
                ah[mt][2] = *(const unsigned*)(pH + 8);
                ah[mt][3] = *(const unsigned*)(pH + 8 * BP + 8);
                al[mt][0] = *(const unsigned*)(pL);
                al[mt][1] = *(const unsigned*)(pL + 8 * BP);
                al[mt][2] = *(const unsigned*)(pL + 8);
                al[mt][3] = *(const unsigned*)(pL + 8 * BP + 8);
            }
#pragma unroll
            for (int nt = 0; nt < 4; ++nt) {
                int n = wn * 32 + nt * 8 + g;
                const __nv_bfloat16* pH = BsHi + n * BP + kk + tig * 2;
                const __nv_bfloat16* pL = BsLo + n * BP + kk + tig * 2;
                unsigned bh0 = *(const unsigned*)(pH);
                unsigned bh1 = *(const unsigned*)(pH + 8);
                unsigned bl0 = *(const unsigned*)(pL);
                unsigned bl1 = *(const unsigned*)(pL + 8);
#pragma unroll
                for (int mt = 0; mt < 4; ++mt) {
                    mma_bf16(acc[mt][nt], ah[mt][0], ah[mt][1], ah[mt][2], ah[mt][3],
                             bh0, bh1);
                    mma_bf16(acc[mt][nt], al[mt][0], al[mt][1], al[mt][2], al[mt][3],
                             bh0, bh1);
                    mma_bf16(acc[mt][nt], ah[mt][0], ah[mt][1], ah[mt][2], ah[mt][3],
                             bl0, bl1);
                }
            }
        }
        __syncthreads();
    }

#pragma unroll
    for (int mt = 0; mt < 4; ++mt) {
#pragma unroll
        for (int nt = 0; nt < 4; ++nt) {
            int jj = bc * 128 + wn * 32 + nt * 8 + tig * 2;
#pragma unroll
            for (int half = 0; half < 2; ++half) {
                int ii = br * 128 + wm * 64 + mt * 16 + g + half * 8;
                float2 val;
                val.x = acc[mt][nt][half * 2 + 0];
                val.y = acc[mt][nt][half * 2 + 1];
                if (GEMM3 == 0) {
                    *(float2*)(C + (long)ii * N + jj) = val;
                } else {
                    int b = ii >> 9, l = ii & 511;
                    int h = jj >> 6, d = jj & 63;
                    *(float2*)(C + (((long)(b * 16 + h) * 512) + l) * 64 + d) = val;
                }
            }
        }
    }
}

// ====================================================================
// Tensor-core flash attention, all-bf16 3-term.
// R14: register-prefetch pipeline — tile kt+1's K/V/mask LDGs are issued
// right after the store-phase sync and consumed (cvt+STS) at the top of
// the next iteration, hiding global latency behind S/softmax/PV compute.
// ====================================================================
#define KP  72
#define VTP 36
#define PP  36
#define QSP 68
#define OFF_KHI 0
#define OFF_KLO 2304
#define OFF_VTH 4608
#define OFF_VTL 6912
#define OFF_PQ  9216
#define OFF_MS  18432
#define ATTN_SMEM_FLOATS 20480            // 81920 B

template<int OUTBF>
__global__ void __launch_bounds__(256, 1) attn_tc(
    const float* __restrict__ Q,
    const float* __restrict__ Kb, long kBS, long kHS, int kRS,
    const float* __restrict__ Vb, long vBS, long vHS, int vRS,
    const unsigned char* __restrict__ mask8,
    float* __restrict__ Ob, long oBS, long oHS, int oRS,
    int residual)
{
    extern __shared__ float sm[];
    __nv_bfloat16* Khi = (__nv_bfloat16*)(sm + OFF_KHI);
    __nv_bfloat16* Klo = (__nv_bfloat16*)(sm + OFF_KLO);
    unsigned* VtHi = (unsigned*)(sm + OFF_VTH);
    unsigned* VtLo = (unsigned*)(sm + OFF_VTL);
    float*    Qs   = sm + OFF_PQ;
    unsigned* PH   = (unsigned*)(sm + OFF_PQ);
    unsigned* PL   = PH + 128 * PP;
    unsigned char* Ms = (unsigned char*)(sm + OFF_MS);

    const int b  = blockIdx.z;
    const int h  = blockIdx.y;
    const int q0 = blockIdx.x * 128;

    const float* Qp = Q + (((long)(b*16 + h) * 512) + q0) * 64;
    const float* Kp = Kb + (long)b * kBS + (long)h * kHS;
    const float* Vp = Vb + (long)b * vBS + (long)h * vHS;
    const unsigned char* Mp = mask8 + (long)b * LL * LL + (long)q0 * LL;
    float* Op = Ob + (long)b * oBS + (long)h * oHS + (long)q0 * oRS;
    __nv_bfloat16* OHi = (__nv_bfloat16*)g_atthi + (long)b * oBS + (long)h * oHS + (long)q0 * oRS;
    __nv_bfloat16* OLo = (__nv_bfloat16*)g_attlo + (long)b * oBS + (long)h * oHS + (long)q0 * oRS;

    const int tid  = threadIdx.x;
    const int w    = tid >> 5;
    const int lane = tid & 31;
    const int g    = lane >> 2;
    const int tig  = lane & 3;
    const int r0   = w * 16 + g;

    // per-thread load coordinates (fixed across tiles)
    const int kf_row[4] = { (tid) >> 4, (tid + 256) >> 4, (tid + 512) >> 4, (tid + 768) >> 4 };
    const int kf_c4 = tid & 15;
    const int vjp0 = tid & 31, vc40 = tid >> 5;          // it=0
    const int vjp1 = vjp0, vc41 = vc40 + 8;              // it=1 (tid+256)

    // ---- stage Q, extract bf16 hi/lo fragments into registers ----
#pragma unroll
    for (int it = 0; it < 8; ++it) {
        int f = tid + it * 256;
        int row = f >> 4, c4 = f & 15;
        float4 v = *(const float4*)(Qp + (long)row * 64 + c4 * 4);
        float* dst = Qs + row * QSP + c4 * 4;
        dst[0] = v.x; dst[1] = v.y; dst[2] = v.z; dst[3] = v.w;
    }
    __syncthreads();

    unsigned qh[4][4], ql[4][4];
#pragma unroll
    for (int kc = 0; kc < 4; ++kc) {
        const float* p0 = Qs + (r0)     * QSP + kc * 16 + tig * 2;
        const float* p1 = Qs + (r0 + 8) * QSP + kc * 16 + tig * 2;
        bsplit2(p0[0] * 0.125f, p0[1] * 0.125f, qh[kc][0], ql[kc][0]);
        bsplit2(p1[0] * 0.125f, p1[1] * 0.125f, qh[kc][1], ql[kc][1]);
        bsplit2(p0[8] * 0.125f, p0[9] * 0.125f, qh[kc][2], ql[kc][2]);
        bsplit2(p1[8] * 0.125f, p1[9] * 0.125f, qh[kc][3], ql[kc][3]);
    }

    float oacc[8][4];
#pragma unroll
    for (int nt = 0; nt < 8; ++nt)
#pragma unroll
        for (int i = 0; i < 4; ++i) oacc[nt][i] = 0.f;

    float m0 = -1e30f, m1 = -1e30f, l0 = 0.f, l1 = 0.f;

    // ---- register prefetch buffers ----
    float4 pk[4];        // K rows
    float4 pva[2], pvb[2]; // V row pairs
    uint4  pm[2];        // mask

    auto prefetch = [&](int k0) {
#pragma unroll
        for (int it = 0; it < 4; ++it)
            pk[it] = *(const float4*)(Kp + (long)(k0 + kf_row[it]) * kRS + kf_c4 * 4);
        {
            const float* v0 = Vp + (long)(k0 + 2 * vjp0) * vRS + vc40 * 4;
            pva[0] = *(const float4*)v0;
            pvb[0] = *(const float4*)(v0 + vRS);
            const float* v1 = Vp + (long)(k0 + 2 * vjp1) * vRS + vc41 * 4;
            pva[1] = *(const float4*)v1;
            pvb[1] = *(const float4*)(v1 + vRS);
        }
#pragma unroll
        for (int it = 0; it < 2; ++it) {
            int u = tid + it * 256;
            int row = u >> 2, c16 = u & 3;
            pm[it] = *(const uint4*)(Mp + (long)row * LL + k0 + c16 * 16);
        }
    };

    prefetch(0);

    for (int kt = 0; kt < 8; ++kt) {
        // ---- store staged tile (cvt from registers) ----
#pragma unroll
        for (int it = 0; it < 4; ++it) {
            int row = kf_row[it];
            unsigned h01, l01, h23, l23;
            bsplit2(pk[it].x, pk[it].y, h01, l01);
            bsplit2(pk[it].z, pk[it].w, h23, l23);
            *(uint2*)(Khi + row * KP + kf_c4 * 4) = make_uint2(h01, h23);
            *(uint2*)(Klo + row * KP + kf_c4 * 4) = make_uint2(l01, l23);
        }
#pragma unroll
        for (int it = 0; it < 2; ++it) {
            int jp = (it == 0) ? vjp0 : vjp1;
            int c4 = (it == 0) ? vc40 : vc41;
            float4 a = pva[it], bq = pvb[it];
            unsigned hh, ll;
            bsplit2(a.x, bq.x, hh, ll);
            VtHi[(c4 * 4 + 0) * VTP + jp] = hh; VtLo[(c4 * 4 + 0) * VTP + jp] = ll;
            bsplit2(a.y, bq.y, hh, ll);
            VtHi[(c4 * 4 + 1) * VTP + jp] = hh; VtLo[(c4 * 4 + 1) * VTP + jp] = ll;
            bsplit2(a.z, bq.z, hh, ll);
            VtHi[(c4 * 4 + 2) * VTP + jp] = hh; VtLo[(c4 * 4 + 2) * VTP + jp] = ll;
            bsplit2(a.w, bq.w, hh, ll);
            VtHi[(c4 * 4 + 3) * VTP + jp] = hh; VtLo[(c4 * 4 + 3) * VTP + jp] = ll;
        }
#pragma unroll
        for (int it = 0; it < 2; ++it) {
            int u = tid + it * 256;
            int row = u >> 2, c16 = u & 3;
            ((uint4*)Ms)[row * 4 + c16] = pm[it];
        }
        __syncthreads();

        // ---- issue next tile's loads (completes during compute) ----
        if (kt + 1 < 8) prefetch((kt + 1) * 64);

        // ---- S = Q K^T (3-term bf16) ----
        float sacc[8][4];
#pragma unroll
        for (int nt = 0; nt < 8; ++nt) {
#pragma unroll
            for (int i = 0; i < 4; ++i) sacc[nt][i] = 0.f;
#pragma unroll
            for (int kc = 0; kc < 4; ++kc) {
                const __nv_bfloat16* pH = Khi + (nt * 8 + g) * KP + kc * 16 + tig * 2;
                const __nv_bfloat16* pL = Klo + (nt * 8 + g) * KP + kc * 16 + tig * 2;
                unsigned bh0 = *(const unsigned*)(pH);
                unsigned bh1 = *(const unsigned*)(pH + 8);
                unsigned bl0 = *(const unsigned*)(pL);
                unsigned bl1 = *(const unsigned*)(pL + 8);
                mma_bf16(sacc[nt], qh[kc][0], qh[kc][1], qh[kc][2], qh[kc][3], bh0, bh1);
                mma_bf16(sacc[nt], ql[kc][0], ql[kc][1], ql[kc][2], ql[kc][3], bh0, bh1);
                mma_bf16(sacc[nt], qh[kc][0], qh[kc][1], qh[kc][2], qh[kc][3], bl0, bl1);
            }
        }

        // ---- mask ----
#pragma unroll
        for (int nt = 0; nt < 8; ++nt) {
            uchar2 mA = *(const uchar2*)(Ms + (r0)     * 64 + nt * 8 + tig * 2);
            uchar2 mB = *(const uchar2*)(Ms + (r0 + 8) * 64 + nt * 8 + tig * 2);
            if (mA.x) sacc[nt][0] = -1e9f;
            if (mA.y) sacc[nt][1] = -1e9f;
            if (mB.x) sacc[nt][2] = -1e9f;
            if (mB.y) sacc[nt][3] = -1e9f;
        }

        // ---- online softmax (warp-local) ----
        float mx0 = -3.0e38f, mx1 = -3.0e38f;
#pragma unroll
        for (int nt = 0; nt < 8; ++nt) {
            mx0 = fmaxf(mx0, fmaxf(sacc[nt][0], sacc[nt][1]));
            mx1 = fmaxf(mx1, fmaxf(sacc[nt][2], sacc[nt][3]));
        }
        mx0 = fmaxf(mx0, __shfl_xor_sync(0xffffffffu, mx0, 1));
        mx0 = fmaxf(mx0, __shfl_xor_sync(0xffffffffu, mx0, 2));
        mx1 = fmaxf(mx1, __shfl_xor_sync(0xffffffffu, mx1, 1));
        mx1 = fmaxf(mx1, __shfl_xor_sync(0xffffffffu, mx1, 2));

        float mn0 = fmaxf(m0, mx0), mn1 = fmaxf(m1, mx1);
        float al0 = __expf(m0 - mn0), al1 = __expf(m1 - mn1);
        m0 = mn0; m1 = mn1;

        float sum0 = 0.f, sum1 = 0.f;
#pragma unroll
        for (int nt = 0; nt < 8; ++nt) {
            float p00 = __expf(sacc[nt][0] - m0);
            float p01 = __expf(sacc[nt][1] - m0);
            float p10 = __expf(sacc[nt][2] - m1);
            float p11 = __expf(sacc[nt][3] - m1);
            sum0 += p00 + p01;
            sum1 += p10 + p11;
            unsigned hh, ll;
            bsplit2(p00, p01, hh, ll);
            PH[(r0)     * PP + nt * 4 + tig] = hh;
            PL[(r0)     * PP + nt * 4 + tig] = ll;
            bsplit2(p10, p11, hh, ll);
            PH[(r0 + 8) * PP + nt * 4 + tig] = hh;
            PL[(r0 + 8) * PP + nt * 4 + tig] = ll;
        }
        sum0 += __shfl_xor_sync(0xffffffffu, sum0, 1);
        sum0 += __shfl_xor_sync(0xffffffffu, sum0, 2);
        sum1 += __shfl_xor_sync(0xffffffffu, sum1, 1);
        sum1 += __shfl_xor_sync(0xffffffffu, sum1, 2);
        l0 = l0 * al0 + sum0;
        l1 = l1 * al1 + sum1;

#pragma unroll
        for (int nt = 0; nt < 8; ++nt) {
            oacc[nt][0] *= al0; oacc[nt][1] *= al0;
            oacc[nt][2] *= al1; oacc[nt][3] *= al1;
        }
        __syncwarp();

        // ---- O += P V (3-term bf16) ----
#pragma unroll
        for (int kc = 0; kc < 4; ++kc) {
            const unsigned* pHr0 = PH + (r0)     * PP + kc * 8 + tig;
            const unsigned* pHr8 = PH + (r0 + 8) * PP + kc * 8 + tig;
            const unsigned* pLr0 = PL + (r0)     * PP + kc * 8 + tig;
            const unsigned* pLr8 = PL + (r0 + 8) * PP + kc * 8 + tig;
            unsigned ph0 = pHr0[0], ph1 = pHr8[0], ph2 = pHr0[4], ph3 = pHr8[4];
            unsigned pl0 = pLr0[0], pl1 = pLr8[0], pl2 = pLr0[4], pl3 = pLr8[4];
#pragma unroll
            for (int nt = 0; nt < 8; ++nt) {
                const unsigned* vH = VtHi + (nt * 8 + g) * VTP + kc * 8 + tig;
                const unsigned* vL = VtLo + (nt * 8 + g) * VTP + kc * 8 + tig;
                unsigned bh0 = vH[0], bh1 = vH[4];
                unsigned bl0 = vL[0], bl1 = vL[4];
                mma_bf16(oacc[nt], ph0, ph1, ph2, ph3, bh0, bh1);
                mma_bf16(oacc[nt], pl0, pl1, pl2, pl3, bh0, bh1);
                mma_bf16(oacc[nt], ph0, ph1, ph2, ph3, bl0, bl1);
            }
        }
        __syncthreads();
    }

    float inv0 = 1.0f / l0, inv1 = 1.0f / l1;
#pragma unroll
    for (int nt = 0; nt < 8; ++nt) {
        int c = nt * 8 + tig * 2;
        float2 v0 = make_float2(oacc[nt][0] * inv0, oacc[nt][1] * inv0);
        float2 v1 = make_float2(oacc[nt][2] * inv1, oacc[nt][3] * inv1);
        if (OUTBF) {
            unsigned hh, ll;
            bsplit2(v0.x, v0.y, hh, ll);
            *(unsigned*)(OHi + (long)(r0) * oRS + c) = hh;
            *(unsigned*)(OLo + (long)(r0) * oRS + c) = ll;
            bsplit2(v1.x, v1.y, hh, ll);
            *(unsigned*)(OHi + (long)(r0 + 8) * oRS + c) = hh;
            *(unsigned*)(OLo + (long)(r0 + 8) * oRS + c) = ll;
        } else {
            if (residual) {
                float2 qres0 = *(const float2*)(Qp + (long)(r0)     * 64 + c);
                float2 qres1 = *(const float2*)(Qp + (long)(r0 + 8) * 64 + c);
                v0.x += qres0.x; v0.y += qres0.y;
                v1.x += qres1.x; v1.y += qres1.y;
            }
            *(float2*)(Op + (long)(r0)     * oRS + c) = v0;
            *(float2*)(Op + (long)(r0 + 8) * oRS + c) = v1;
        }
    }
}

// ====================================================================
extern "C" void kernel_launch(void* const* d_in, const int* in_sizes, int n_in,
                              void* d_out, int out_size)
{
    (void)in_sizes; (void)n_in; (void)out_size;
    const float* v   = (const float*)d_in[0];
    const float* k   = (const float*)d_in[1];
    const float* q   = (const float*)d_in[2];
    const float* img = (const float*)d_in[3];
    const float* Wv  = (const float*)d_in[4];
    const float* Wk  = (const float*)d_in[5];
    const float* Wq  = (const float*)d_in[6];
    const float* Wm  = (const float*)d_in[7];
    const uint4* absm = (const uint4*)d_in[8];
    const uint4* mask = (const uint4*)d_in[9];
    float* out = (float*)d_out;

    float *vh, *kh, *qh, *qn;
    unsigned char *absm8, *mask8;
    cudaGetSymbolAddress((void**)&vh,  g_vh);
    cudaGetSymbolAddress((void**)&kh,  g_kh);
    cudaGetSymbolAddress((void**)&qh,  g_qh);
    cudaGetSymbolAddress((void**)&qn,  g_qn);
    cudaGetSymbolAddress((void**)&absm8, g_absm8);
    cudaGetSymbolAddress((void**)&mask8, g_mask8);

    pack_masks<<<4096, 256>>>(absm, mask, (uchar4*)absm8, (uchar4*)mask8);
    dim3 gi(MROWS * HS / 4 / 256, 3);
    pack_in<<<gi, 256>>>((const float4*)v, (const float4*)k, (const float4*)q);
    dim3 gw(HS * HS / 4 / 256, 4);
    pack_w<<<gw, 256>>>((const float4*)Wv, (const float4*)Wk,
                        (const float4*)Wq, (const float4*)Wm);

    const int gsmem = 2 * STG * (int)sizeof(__nv_bfloat16);   // 81920
    cudaFuncSetAttribute(gemm_pre<0>,
                         cudaFuncAttributeMaxDynamicSharedMemorySize, gsmem);
    cudaFuncSetAttribute(gemm_pre<1>,
                         cudaFuncAttributeMaxDynamicSharedMemorySize, gsmem);

    dim3 g3(HS / 128, MROWS / 128, 3);   // (8, 64, 3)
    gemm_pre<1><<<g3, 256, gsmem>>>(nullptr, MROWS, HS, HS);

    const int asmem = ATTN_SMEM_FLOATS * (int)sizeof(float);
    cudaFuncSetAttribute(attn_tc<0>,
                         cudaFuncAttributeMaxDynamicSharedMemorySize, asmem);
    cudaFuncSetAttribute(attn_tc<1>,
                         cudaFuncAttributeMaxDynamicSharedMemorySize, asmem);

    dim3 ga(LL / 128, HH, BB);
    attn_tc<0><<<ga, 256, asmem>>>(
        qh,
        img, (long)LL * HS, 64L, HS,
        img, (long)LL * HS, 64L, HS,
        absm8,
        qn,  (long)HH * LL * DD, (long)LL * DD, DD,
        1);
    attn_tc<1><<<ga, 256, asmem>>>(
        qn,
        kh, (long)HH * LL * DD, (long)LL * DD, DD,
        vh, (long)HH * LL * DD, (long)LL * DD, DD,
        mask8,
        nullptr, (long)LL * HS, 64L, HS,
        0);

    dim3 gg(HS / 128, MROWS / 128);   // (8, 64)
    gemm_pre<0><<<gg, 256, gsmem>>>(out, MROWS, HS, HS);
}

// round 15
// speedup vs baseline: 1.6207x; 1.0033x over previous
#include <cuda_runtime.h>
#include <cuda_bf16.h>

// Problem constants
#define BB 16
#define LL 512
#define HS 1024
#define HH 16
#define DD 64
#define MROWS (BB*LL)        // 8192

// -------------------- scratch (allocation-free) --------------------
__device__ float g_vh[BB*HH*LL*DD];   // [B,H,L,D]
__device__ float g_kh[BB*HH*LL*DD];
__device__ float g_qh[BB*HH*LL*DD];
__device__ unsigned char g_absm8[BB*LL*LL];
__device__ unsigned char g_mask8[BB*LL*LL];
__device__ uint4 g_inhi[3L*MROWS*HS/8];
__device__ uint4 g_inlo[3L*MROWS*HS/8];
__device__ uint4 g_whi[4L*HS*HS/8];
__device__ uint4 g_wlo[4L*HS*HS/8];
__device__ uint4 g_atthi[(long)MROWS*HS/8];
__device__ uint4 g_attlo[(long)MROWS*HS/8];

// ------------------ bf16 helpers ------------------
__device__ __forceinline__ unsigned pack2bf(__nv_bfloat16 a, __nv_bfloat16 b) {
    __nv_bfloat162 t; t.x = a; t.y = b;
    return reinterpret_cast<unsigned&>(t);
}

__device__ __forceinline__ void bsplit2(float x0, float x1, unsigned &hi, unsigned &lo) {
    __nv_bfloat16 h0 = __float2bfloat16(x0);
    __nv_bfloat16 h1 = __float2bfloat16(x1);
    __nv_bfloat16 l0 = __float2bfloat16(x0 - __bfloat162float(h0));
    __nv_bfloat16 l1 = __float2bfloat16(x1 - __bfloat162float(h1));
    hi = pack2bf(h0, h1);
    lo = pack2bf(l0, l1);
}

__device__ __forceinline__ void mma_bf16(float d[4],
                                         unsigned a0, unsigned a1, unsigned a2, unsigned a3,
                                         unsigned b0, unsigned b1)
{
    asm volatile(
        "mma.sync.aligned.m16n8k16.row.col.f32.bf16.bf16.f32 "
        "{%0,%1,%2,%3}, {%4,%5,%6,%7}, {%8,%9}, {%0,%1,%2,%3};\n"
        : "+f"(d[0]), "+f"(d[1]), "+f"(d[2]), "+f"(d[3])
        : "r"(a0), "r"(a1), "r"(a2), "r"(a3), "r"(b0), "r"(b1));
}

__device__ __forceinline__ void cp16(void* smem_dst, const void* gmem_src) {
    unsigned s = (unsigned)__cvta_generic_to_shared(smem_dst);
    asm volatile("cp.async.cg.shared.global [%0], [%1], 16;\n"
                 :: "r"(s), "l"(gmem_src) : "memory");
}
#define CP_COMMIT() asm volatile("cp.async.commit_group;\n" ::: "memory")
#define CP_WAIT(n)  asm volatile("cp.async.wait_group %0;\n" :: "n"(n) : "memory")

// ====================================================================
// Prepack kernels
// ====================================================================
__global__ void __launch_bounds__(256) pack_masks(const uint4* __restrict__ a,
                                                  const uint4* __restrict__ b,
                                                  uchar4* __restrict__ oa,
                                                  uchar4* __restrict__ ob)
{
    int i = blockIdx.x * blockDim.x + threadIdx.x;
    uint4 x = a[i];
    oa[i] = make_uchar4(x.x ? 1 : 0, x.y ? 1 : 0, x.z ? 1 : 0, x.w ? 1 : 0);
    uint4 y = b[i];
    ob[i] = make_uchar4(y.x ? 1 : 0, y.y ? 1 : 0, y.z ? 1 : 0, y.w ? 1 : 0);
}

__global__ void __launch_bounds__(256) pack_in(const float4* __restrict__ v,
                                               const float4* __restrict__ k,
                                               const float4* __restrict__ q)
{
    int z = blockIdx.y;
    const float4* src = (z == 0) ? v : (z == 1) ? k : q;
    long i = (long)blockIdx.x * 256 + threadIdx.x;
    float4 x = src[i];
    unsigned h01, l01, h23, l23;
    bsplit2(x.x, x.y, h01, l01);
    bsplit2(x.z, x.w, h23, l23);
    long d = (long)z * (MROWS * (long)HS / 4) + i;
    ((uint2*)g_inhi)[d] = make_uint2(h01, h23);
    ((uint2*)g_inlo)[d] = make_uint2(l01, l23);
}

__global__ void __launch_bounds__(256) pack_w(const float4* __restrict__ w0,
                                              const float4* __restrict__ w1,
                                              const float4* __restrict__ w2,
                                              const float4* __restrict__ w3)
{
    int z = blockIdx.y;
    const float4* src = (z == 0) ? w0 : (z == 1) ? w1 : (z == 2) ? w2 : w3;
    long i = (long)blockIdx.x * 256 + threadIdx.x;
    float4 x = src[i];
    unsigned h01, l01, h23, l23;
    bsplit2(x.x, x.y, h01, l01);
    bsplit2(x.z, x.w, h23, l23);
    long d = (long)z * ((long)HS * HS / 4) + i;
    ((uint2*)g_whi)[d] = make_uint2(h01, h23);
    ((uint2*)g_wlo)[d] = make_uint2(l01, l23);
}

// ====================================================================
// bf16 GEMM (R13 config, GEMM plateau): 128x128 tile, cp.async, 2 CTAs/SM.
// ====================================================================
#define BP 40
#define STG (4*128*BP)

template<int GEMM3>
__global__ void __launch_bounds__(256, 2) gemm_pre(float* __restrict__ Cout,
                                                   int M, int N, int K)
{
    extern __shared__ float smf[];
    __nv_bfloat16* smb = (__nv_bfloat16*)smf;

    const __nv_bfloat16 *Ahi, *Alo, *Whi, *Wlo;
    float* C;
    if (GEMM3) {
        int z = blockIdx.z;
        Ahi = (const __nv_bfloat16*)g_inhi + (long)z * MROWS * HS;
        Alo = (const __nv_bfloat16*)g_inlo + (long)z * MROWS * HS;
        Whi = (const __nv_bfloat16*)g_whi + (long)z * HS * HS;
        Wlo = (const __nv_bfloat16*)g_wlo + (long)z * HS * HS;
        C   = (z == 0) ? g_vh : (z == 1) ? g_kh : g_qh;
    } else {
        Ahi = (const __nv_bfloat16*)g_atthi;
        Alo = (const __nv_bfloat16*)g_attlo;
        Whi = (const __nv_bfloat16*)g_whi + 3L * HS * HS;
        Wlo = (const __nv_bfloat16*)g_wlo + 3L * HS * HS;
        C   = Cout;
    }

    const int tid  = threadIdx.x;
    const int br   = blockIdx.y;
    const int bc   = blockIdx.x;
    const int wid  = tid >> 5;
    const int lane = tid & 31;
    const int g    = lane >> 2;
    const int tig  = lane & 3;
    const int wm   = wid >> 2;
    const int wn   = wid & 3;

    const __nv_bfloat16* AbH = Ahi + (long)br * 128 * K;
    const __nv_bfloat16* AbL = Alo + (long)br * 128 * K;
    const __nv_bfloat16* BbH = Whi + (long)bc * 128 * K;
    const __nv_bfloat16* BbL = Wlo + (long)bc * 128 * K;

    float acc[4][4][4];
#pragma unroll
    for (int mt = 0; mt < 4; ++mt)
#pragma unroll
        for (int nt = 0; nt < 4; ++nt)
#pragma unroll
            for (int r = 0; r < 4; ++r) acc[mt][nt][r] = 0.f;

    auto issue = [&](int s, int kb) {
        __nv_bfloat16* AsHi = smb + s * STG;
        __nv_bfloat16* AsLo = AsHi + 128 * BP;
        __nv_bfloat16* BsHi = AsLo + 128 * BP;
        __nv_bfloat16* BsLo = BsHi + 128 * BP;
#pragma unroll
        for (int i = 0; i < 2; ++i) {
            int ch = tid + i * 256;
            int row = ch >> 2, seg = ch & 3;
            long go = (long)row * K + kb + seg * 8;
            int  so = row * BP + seg * 8;
            cp16(AsHi + so, AbH + go);
            cp16(AsLo + so, AbL + go);
            cp16(BsHi + so, BbH + go);
            cp16(BsLo + so, BbL + go);
        }
        CP_COMMIT();
    };

    issue(0, 0);

    const int nKt = K / 32;
    for (int kt = 0; kt < nKt; ++kt) {
        const int s = kt & 1;
        if (kt + 1 < nKt) {
            issue(s ^ 1, (kt + 1) * 32);
            CP_WAIT(1);
        } else {
            CP_WAIT(0);
        }
        __syncthreads();

        const __nv_bfloat16* AsHi = smb + s * STG;
        const __nv_bfloat16* AsLo = AsHi + 128 * BP;
        const __nv_bfloat16* BsHi = AsLo + 128 * BP;
        const __nv_bfloat16* BsLo = BsHi + 128 * BP;

#pragma unroll
        for (int ks = 0; ks < 2; ++ks) {
            const int kk = ks * 16;
            unsigned ah[4][4], al[4][4];
#pragma unroll
            for (int mt = 0; mt < 4; ++mt) {
                int m = wm * 64 + mt * 16 + g;
                const __nv_bfloat16* pH = AsHi + m * BP + kk + tig * 2;
                const __nv_bfloat16* pL = AsLo + m * BP + kk + tig * 2;
                ah[mt][0] = *(const unsigned*)(pH);
                ah[mt][1] = *(const unsigned*)(pH + 8 * BP);
                ah[mt][2] = *(const unsigned*)(pH + 8);
                ah[mt][3] = *(const unsigned*)(pH + 8 * BP + 8);
                al[mt][0] = *(const unsigned*)(pL);
                al[mt][1] = *(const unsigned*)(pL + 8 * BP);
                al[mt][2] = *(const unsigned*)(pL + 8);
                al[mt][3] = *(const unsigned*)(pL + 8 * BP + 8);
            }
#pragma unroll
            for (int nt = 0; nt < 4; ++nt) {
                int n = wn * 32 + nt * 8 + g;
                const __nv_bfloat16* pH = BsHi + n * BP + kk + tig * 2;
                const __nv_bfloat16* pL = BsLo + n * BP + kk + tig * 2;
                unsigned bh0 = *(const unsigned*)(pH);
                unsigned bh1 = *(const unsigned*)(pH + 8);
                unsigned bl0 = *(const unsigned*)(pL);
                unsigned bl1 = *(const unsigned*)(pL + 8);
#pragma unroll
                for (int mt = 0; mt < 4; ++mt) {
                    mma_bf16(acc[mt][nt], ah[mt][0], ah[mt][1], ah[mt][2], ah[mt][3],
                             bh0, bh1);
                    mma_bf16(acc[mt][nt], al[mt][0], al[mt][1], al[mt][2], al[mt][3],
                             bh0, bh1);
                    mma_bf16(acc[mt][nt], ah[mt][0], ah[mt][1], ah[mt][2], ah[mt][3],
                             bl0, bl1);
                }
            }
        }
        __syncthreads();
    }

#pragma unroll
    for (int mt = 0; mt < 4; ++mt) {
#pragma unroll
        for (int nt = 0; nt < 4; ++nt) {
            int jj = bc * 128 + wn * 32 + nt * 8 + tig * 2;
#pragma unroll
            for (int half = 0; half < 2; ++half) {
                int ii = br * 128 + wm * 64 + mt * 16 + g + half * 8;
                float2 val;
                val.x = acc[mt][nt][half * 2 + 0];
                val.y = acc[mt][nt][half * 2 + 1];
                if (GEMM3 == 0) {
                    *(float2*)(C + (long)ii * N + jj) = val;
                } else {
                    int b = ii >> 9, l = ii & 511;
                    int h = jj >> 6, d = jj & 63;
                    *(float2*)(C + (((long)(b * 16 + h) * 512) + l) * 64 + d) = val;
                }
            }
        }
    }
}

// ====================================================================
// FUSED two-stage tensor-core flash attention (all-bf16 3-term).
// Stage 1 (modulate vs img_abs/absm) -> qn held in REGISTERS (oacc layout
// maps exactly onto Q-fragment layout: nt = 2*kc, 2*kc+1) -> Stage 2
// (main attention vs kh/vh/mask) -> bf16 hi/lo epilogue to g_att{hi,lo}.
// Register-prefetch pipeline spans both stages (stage-2 tile 0 prefetched
// during stage-1 tile 7 compute).
// ====================================================================
#define KP  72
#define VTP 36
#define PP  36
#define QSP 68
#define OFF_KHI 0
#define OFF_KLO 2304
#define OFF_VTH 4608
#define OFF_VTL 6912
#define OFF_PQ  9216
#define OFF_MS  18432
#define ATTN_SMEM_FLOATS 20480            // 81920 B

__global__ void __launch_bounds__(256, 1) attn_fused(
    const float* __restrict__ Qg,          // g_qh [B,H,L,D]
    const float* __restrict__ img,         // [B,L,HS]
    const unsigned char* __restrict__ absm8,
    const float* __restrict__ kh,          // [B,H,L,D]
    const float* __restrict__ vh,          // [B,H,L,D]
    const unsigned char* __restrict__ mask8)
{
    extern __shared__ float sm[];
    __nv_bfloat16* Khi = (__nv_bfloat16*)(sm + OFF_KHI);
    __nv_bfloat16* Klo = (__nv_bfloat16*)(sm + OFF_KLO);
    unsigned* VtHi = (unsigned*)(sm + OFF_VTH);
    unsigned* VtLo = (unsigned*)(sm + OFF_VTL);
    float*    Qs   = sm + OFF_PQ;
    unsigned* PH   = (unsigned*)(sm + OFF_PQ);
    unsigned* PL   = PH + 128 * PP;
    unsigned char* Ms = (unsigned char*)(sm + OFF_MS);

    const int b  = blockIdx.z;
    const int h  = blockIdx.y;
    const int q0 = blockIdx.x * 128;

    const float* Qp  = Qg + (((long)(b*16 + h) * 512) + q0) * 64;
    // phase pointers / strides
    const float* Kbase[2];
    const float* Vbase[2];
    const unsigned char* Mbase[2];
    int rstride[2];
    Kbase[0] = img + (long)b * LL * HS + h * 64;   rstride[0] = HS;
    Vbase[0] = Kbase[0];
    Mbase[0] = absm8 + (long)b * LL * LL + (long)q0 * LL;
    Kbase[1] = kh + (((long)(b*16 + h) * 512)) * 64;  rstride[1] = DD;
    Vbase[1] = vh + (((long)(b*16 + h) * 512)) * 64;
    Mbase[1] = mask8 + (long)b * LL * LL + (long)q0 * LL;

    __nv_bfloat16* OHi = (__nv_bfloat16*)g_atthi + (long)b * LL * HS + h * 64 + (long)q0 * HS;
    __nv_bfloat16* OLo = (__nv_bfloat16*)g_attlo + (long)b * LL * HS + h * 64 + (long)q0 * HS;

    const int tid  = threadIdx.x;
    const int w    = tid >> 5;
    const int lane = tid & 31;
    const int g    = lane >> 2;
    const int tig  = lane & 3;
    const int r0   = w * 16 + g;

    const int kf_row[4] = { (tid) >> 4, (tid + 256) >> 4, (tid + 512) >> 4, (tid + 768) >> 4 };
    const int kf_c4 = tid & 15;
    const int vjp0 = tid & 31, vc40 = tid >> 5;
    const int vjp1 = vjp0, vc41 = vc40 + 8;

    // ---- stage Q, extract bf16 hi/lo fragments (with 0.125 scale) ----
#pragma unroll
    for (int it = 0; it < 8; ++it) {
        int f = tid + it * 256;
        int row = f >> 4, c4 = f & 15;
        float4 v = *(const float4*)(Qp + (long)row * 64 + c4 * 4);
        float* dst = Qs + row * QSP + c4 * 4;
        dst[0] = v.x; dst[1] = v.y; dst[2] = v.z; dst[3] = v.w;
    }
    __syncthreads();

    unsigned qh[4][4], ql[4][4];
#pragma unroll
    for (int kc = 0; kc < 4; ++kc) {
        const float* p0 = Qs + (r0)     * QSP + kc * 16 + tig * 2;
        const float* p1 = Qs + (r0 + 8) * QSP + kc * 16 + tig * 2;
        bsplit2(p0[0] * 0.125f, p0[1] * 0.125f, qh[kc][0], ql[kc][0]);
        bsplit2(p1[0] * 0.125f, p1[1] * 0.125f, qh[kc][1], ql[kc][1]);
        bsplit2(p0[8] * 0.125f, p0[9] * 0.125f, qh[kc][2], ql[kc][2]);
        bsplit2(p1[8] * 0.125f, p1[9] * 0.125f, qh[kc][3], ql[kc][3]);
    }

    float oacc[8][4];
#pragma unroll
    for (int nt = 0; nt < 8; ++nt)
#pragma unroll
        for (int i = 0; i < 4; ++i) oacc[nt][i] = 0.f;

    float m0 = -1e30f, m1 = -1e30f, l0 = 0.f, l1 = 0.f;

    float4 pk[4];
    float4 pva[2], pvb[2];
    uint4  pm[2];

    auto prefetch = [&](int ph, int k0) {
        const float* Kp = Kbase[ph];
        const float* Vp = Vbase[ph];
        const unsigned char* Mp = Mbase[ph];
        const int rs = rstride[ph];
#pragma unroll
        for (int it = 0; it < 4; ++it)
            pk[it] = *(const float4*)(Kp + (long)(k0 + kf_row[it]) * rs + kf_c4 * 4);
        {
            const float* v0 = Vp + (long)(k0 + 2 * vjp0) * rs + vc40 * 4;
            pva[0] = *(const float4*)v0;
            pvb[0] = *(const float4*)(v0 + rs);
            const float* v1 = Vp + (long)(k0 + 2 * vjp1) * rs + vc41 * 4;
            pva[1] = *(const float4*)v1;
            pvb[1] = *(const float4*)(v1 + rs);
        }
#pragma unroll
        for (int it = 0; it < 2; ++it) {
            int u = tid + it * 256;
            int row = u >> 2, c16 = u & 3;
            pm[it] = *(const uint4*)(Mp + (long)row * LL + k0 + c16 * 16);
        }
    };

    prefetch(0, 0);

    for (int phase = 0; phase < 2; ++phase) {
        for (int kt = 0; kt < 8; ++kt) {
            // ---- store staged tile (cvt from registers) ----
#pragma unroll
            for (int it = 0; it < 4; ++it) {
                int row = kf_row[it];
                unsigned h01, l01, h23, l23;
                bsplit2(pk[it].x, pk[it].y, h01, l01);
                bsplit2(pk[it].z, pk[it].w, h23, l23);
                *(uint2*)(Khi + row * KP + kf_c4 * 4) = make_uint2(h01, h23);
                *(uint2*)(Klo + row * KP + kf_c4 * 4) = make_uint2(l01, l23);
            }
#pragma unroll
            for (int it = 0; it < 2; ++it) {
                int jp = (it == 0) ? vjp0 : vjp1;
                int c4 = (it == 0) ? vc40 : vc41;
                float4 a = pva[it], bq = pvb[it];
                unsigned hh, ll;
                bsplit2(a.x, bq.x, hh, ll);
                VtHi[(c4 * 4 + 0) * VTP + jp] = hh; VtLo[(c4 * 4 + 0) * VTP + jp] = ll;
                bsplit2(a.y, bq.y, hh, ll);
                VtHi[(c4 * 4 + 1) * VTP + jp] = hh; VtLo[(c4 * 4 + 1) * VTP + jp] = ll;
                bsplit2(a.z, bq.z, hh, ll);
                VtHi[(c4 * 4 + 2) * VTP + jp] = hh; VtLo[(c4 * 4 + 2) * VTP + jp] = ll;
                bsplit2(a.w, bq.w, hh, ll);
                VtHi[(c4 * 4 + 3) * VTP + jp] = hh; VtLo[(c4 * 4 + 3) * VTP + jp] = ll;
            }
#pragma unroll
            for (int it = 0; it < 2; ++it) {
                int u = tid + it * 256;
                int row = u >> 2, c16 = u & 3;
                ((uint4*)Ms)[row * 4 + c16] = pm[it];
            }
            __syncthreads();

            // ---- prefetch next tile (possibly of next phase) ----
            if (kt + 1 < 8)          prefetch(phase, (kt + 1) * 64);
            else if (phase == 0)     prefetch(1, 0);

            // ---- S = Q K^T (3-term bf16) ----
            float sacc[8][4];
#pragma unroll
            for (int nt = 0; nt < 8; ++nt) {
#pragma unroll
                for (int i = 0; i < 4; ++i) sacc[nt][i] = 0.f;
#pragma unroll
                for (int kc = 0; kc < 4; ++kc) {
                    const __nv_bfloat16* pH = Khi + (nt * 8 + g) * KP + kc * 16 + tig * 2;
                    const __nv_bfloat16* pL = Klo + (nt * 8 + g) * KP + kc * 16 + tig * 2;
                    unsigned bh0 = *(const unsigned*)(pH);
                    unsigned bh1 = *(const unsigned*)(pH + 8);
                    unsigned bl0 = *(const unsigned*)(pL);
                    unsigned bl1 = *(const unsigned*)(pL + 8);
                    mma_bf16(sacc[nt], qh[kc][0], qh[kc][1], qh[kc][2], qh[kc][3], bh0, bh1);
                    mma_bf16(sacc[nt], ql[kc][0], ql[kc][1], ql[kc][2], ql[kc][3], bh0, bh1);
                    mma_bf16(sacc[nt], qh[kc][0], qh[kc][1], qh[kc][2], qh[kc][3], bl0, bl1);
                }
            }

            // ---- mask ----
#pragma unroll
            for (int nt = 0; nt < 8; ++nt) {
                uchar2 mA = *(const uchar2*)(Ms + (r0)     * 64 + nt * 8 + tig * 2);
                uchar2 mB = *(const uchar2*)(Ms + (r0 + 8) * 64 + nt * 8 + tig * 2);
                if (mA.x) sacc[nt][0] = -1e9f;
                if (mA.y) sacc[nt][1] = -1e9f;
                if (mB.x) sacc[nt][2] = -1e9f;
                if (mB.y) sacc[nt][3] = -1e9f;
            }

            // ---- online softmax (warp-local) ----
            float mx0 = -3.0e38f, mx1 = -3.0e38f;
#pragma unroll
            for (int nt = 0; nt < 8; ++nt) {
                mx0 = fmaxf(mx0, fmaxf(sacc[nt][0], sacc[nt][1]));
                mx1 = fmaxf(mx1, fmaxf(sacc[nt][2], sacc[nt][3]));
            }
            mx0 = fmaxf(mx0, __shfl_xor_sync(0xffffffffu, mx0, 1));
            mx0 = fmaxf(mx0, __shfl_xor_sync(0xffffffffu, mx0, 2));
            mx1 = fmaxf(mx1, __shfl_xor_sync(0xffffffffu, mx1, 1));
            mx1 = fmaxf(mx1, __shfl_xor_sync(0xffffffffu, mx1, 2));

            float mn0 = fmaxf(m0, mx0), mn1 = fmaxf(m1, mx1);
            float al0 = __expf(m0 - mn0), al1 = __expf(m1 - mn1);
            m0 = mn0; m1 = mn1;

            float sum0 = 0.f, sum1 = 0.f;
#pragma unroll
            for (int nt = 0; nt < 8; ++nt) {
                float p00 = __expf(sacc[nt][0] - m0);
                float p01 = __expf(sacc[nt][1] - m0);
                float p10 = __expf(sacc[nt][2] - m1);
                float p11 = __expf(sacc[nt][3] - m1);
                sum0 += p00 + p01;
                sum1 += p10 + p11;
                unsigned hh, ll;
                bsplit2(p00, p01, hh, ll);
                PH[(r0)     * PP + nt * 4 + tig] = hh;
                PL[(r0)     * PP + nt * 4 + tig] = ll;
                bsplit2(p10, p11, hh, ll);
                PH[(r0 + 8) * PP + nt * 4 + tig] = hh;
                PL[(r0 + 8) * PP + nt * 4 + tig] = ll;
            }
            sum0 += __shfl_xor_sync(0xffffffffu, sum0, 1);
            sum0 += __shfl_xor_sync(0xffffffffu, sum0, 2);
            sum1 += __shfl_xor_sync(0xffffffffu, sum1, 1);
            sum1 += __shfl_xor_sync(0xffffffffu, sum1, 2);
            l0 = l0 * al0 + sum0;
            l1 = l1 * al1 + sum1;

#pragma unroll
            for (int nt = 0; nt < 8; ++nt) {
                oacc[nt][0] *= al0; oacc[nt][1] *= al0;
                oacc[nt][2] *= al1; oacc[nt][3] *= al1;
            }
            __syncwarp();

            // ---- O += P V (3-term bf16) ----
#pragma unroll
            for (int kc = 0; kc < 4; ++kc) {
                const unsigned* pHr0 = PH + (r0)     * PP + kc * 8 + tig;
                const unsigned* pHr8 = PH + (r0 + 8) * PP + kc * 8 + tig;
                const unsigned* pLr0 = PL + (r0)     * PP + kc * 8 + tig;
                const unsigned* pLr8 = PL + (r0 + 8) * PP + kc * 8 + tig;
                unsigned ph0 = pHr0[0], ph1 = pHr8[0], ph2 = pHr0[4], ph3 = pHr8[4];
                unsigned pl0 = pLr0[0], pl1 = pLr8[0], pl2 = pLr0[4], pl3 = pLr8[4];
#pragma unroll
                for (int nt = 0; nt < 8; ++nt) {
                    const unsigned* vH = VtHi + (nt * 8 + g) * VTP + kc * 8 + tig;
                    const unsigned* vL = VtLo + (nt * 8 + g) * VTP + kc * 8 + tig;
                    unsigned bh0 = vH[0], bh1 = vH[4];
                    unsigned bl0 = vL[0], bl1 = vL[4];
                    mma_bf16(oacc[nt], ph0, ph1, ph2, ph3, bh0, bh1);
                    mma_bf16(oacc[nt], pl0, pl1, pl2, pl3, bh0, bh1);
                    mma_bf16(oacc[nt], ph0, ph1, ph2, ph3, bl0, bl1);
                }
            }
            __syncthreads();
        }

        if (phase == 0) {
            // ---- inter-stage: qn = oacc/l + Q residual, rebuild Q frags ----
            float inv0 = 1.0f / l0, inv1 = 1.0f / l1;
            float qn0[8][2], qn1[8][2];
#pragma unroll
            for (int nt = 0; nt < 8; ++nt) {
                int c = nt * 8 + tig * 2;
                float2 qr0 = *(const float2*)(Qp + (long)(r0)     * 64 + c);
                float2 qr1 = *(const float2*)(Qp + (long)(r0 + 8) * 64 + c);
                qn0[nt][0] = oacc[nt][0] * inv0 + qr0.x;
                qn0[nt][1] = oacc[nt][1] * inv0 + qr0.y;
                qn1[nt][0] = oacc[nt][2] * inv1 + qr1.x;
                qn1[nt][1] = oacc[nt][3] * inv1 + qr1.y;
            }
            // fragment map: k = kc*16 + tig*2 (+8) -> nt = 2kc (2kc+1)
#pragma unroll
            for (int kc = 0; kc < 4; ++kc) {
                bsplit2(qn0[2*kc][0]   * 0.125f, qn0[2*kc][1]   * 0.125f, qh[kc][0], ql[kc][0]);
                bsplit2(qn1[2*kc][0]   * 0.125f, qn1[2*kc][1]   * 0.125f, qh[kc][1], ql[kc][1]);
                bsplit2(qn0[2*kc+1][0] * 0.125f, qn0[2*kc+1][1] * 0.125f, qh[kc][2], ql[kc][2]);
                bsplit2(qn1[2*kc+1][0] * 0.125f, qn1[2*kc+1][1] * 0.125f, qh[kc][3], ql[kc][3]);
            }
            // reset softmax state
            m0 = -1e30f; m1 = -1e30f; l0 = 0.f; l1 = 0.f;
#pragma unroll
            for (int nt = 0; nt < 8; ++nt)
#pragma unroll
                for (int i = 0; i < 4; ++i) oacc[nt][i] = 0.f;
        }
    }

    // ---- epilogue: bf16 hi/lo to g_att{hi,lo} [B,L,H*D] ----
    float inv0 = 1.0f / l0, inv1 = 1.0f / l1;
#pragma unroll
    for (int nt = 0; nt < 8; ++nt) {
        int c = nt * 8 + tig * 2;
        unsigned hh, ll;
        bsplit2(oacc[nt][0] * inv0, oacc[nt][1] * inv0, hh, ll);
        *(unsigned*)(OHi + (long)(r0) * HS + c) = hh;
        *(unsigned*)(OLo + (long)(r0) * HS + c) = ll;
        bsplit2(oacc[nt][2] * inv1, oacc[nt][3] * inv1, hh, ll);
        *(unsigned*)(OHi + (long)(r0 + 8) * HS + c) = hh;
        *(unsigned*)(OLo + (long)(r0 + 8) * HS + c) = ll;
    }
}

// ====================================================================
extern "C" void kernel_launch(void* const* d_in, const int* in_sizes, int n_in,
                              void* d_out, int out_size)
{
    (void)in_sizes; (void)n_in; (void)out_size;
    const float* v   = (const float*)d_in[0];
    const float* k   = (const float*)d_in[1];
    const float* q   = (const float*)d_in[2];
    const float* img = (const float*)d_in[3];
    const float* Wv  = (const float*)d_in[4];
    const float* Wk  = (const float*)d_in[5];
    const float* Wq  = (const float*)d_in[6];
    const float* Wm  = (const float*)d_in[7];
    const uint4* absm = (const uint4*)d_in[8];
    const uint4* mask = (const uint4*)d_in[9];
    float* out = (float*)d_out;

    float *vh, *kh, *qh;
    unsigned char *absm8, *mask8;
    cudaGetSymbolAddress((void**)&vh,  g_vh);
    cudaGetSymbolAddress((void**)&kh,  g_kh);
    cudaGetSymbolAddress((void**)&qh,  g_qh);
    cudaGetSymbolAddress((void**)&absm8, g_absm8);
    cudaGetSymbolAddress((void**)&mask8, g_mask8);

    pack_masks<<<4096, 256>>>(absm, mask, (uchar4*)absm8, (uchar4*)mask8);
    dim3 gi(MROWS * HS / 4 / 256, 3);
    pack_in<<<gi, 256>>>((const float4*)v, (const float4*)k, (const float4*)q);
    dim3 gw(HS * HS / 4 / 256, 4);
    pack_w<<<gw, 256>>>((const float4*)Wv, (const float4*)Wk,
                        (const float4*)Wq, (const float4*)Wm);

    const int gsmem = 2 * STG * (int)sizeof(__nv_bfloat16);   // 81920
    cudaFuncSetAttribute(gemm_pre<0>,
                         cudaFuncAttributeMaxDynamicSharedMemorySize, gsmem);
    cudaFuncSetAttribute(gemm_pre<1>,
                         cudaFuncAttributeMaxDynamicSharedMemorySize, gsmem);

    dim3 g3(HS / 128, MROWS / 128, 3);   // (8, 64, 3)
    gemm_pre<1><<<g3, 256, gsmem>>>(nullptr, MROWS, HS, HS);

    const int asmem = ATTN_SMEM_FLOATS * (int)sizeof(float);
    cudaFuncSetAttribute(attn_fused,
                         cudaFuncAttributeMaxDynamicSharedMemorySize, asmem);

    dim3 ga(LL / 128, HH, BB);   // (4, 16, 16)
    attn_fused<<<ga, 256, asmem>>>(qh, img, absm8, kh, vh, mask8);

    dim3 gg(HS / 128, MROWS / 128);   // (8, 64)
    gemm_pre<0><<<gg, 256, gsmem>>>(out, MROWS, HS, HS);
}

// round 16
// speedup vs baseline: 1.6750x; 1.0335x over previous
#include <cuda_runtime.h>
#include <cuda_bf16.h>

// Problem constants
#define BB 16
#define LL 512
#define HS 1024
#define HH 16
#define DD 64
#define MROWS (BB*LL)        // 8192

// -------------------- scratch (allocation-free) --------------------
__device__ float g_vh[BB*HH*LL*DD];   // [B,H,L,D]
__device__ float g_kh[BB*HH*LL*DD];
__device__ float g_qh[BB*HH*LL*DD];
__device__ unsigned char g_absm8[BB*LL*LL];
__device__ unsigned char g_mask8[BB*LL*LL];
__device__ uint4 g_inhi[3L*MROWS*HS/8];
__device__ uint4 g_inlo[3L*MROWS*HS/8];
__device__ uint4 g_whi[4L*HS*HS/8];
__device__ uint4 g_wlo[4L*HS*HS/8];
__device__ uint4 g_atthi[(long)MROWS*HS/8];
__device__ uint4 g_attlo[(long)MROWS*HS/8];

// Q pre-scale: 0.125 (1/sqrt(64)) * log2(e)  -> softmax done in exp2 domain
#define QSCALE 0.1803368801111244f

// ------------------ bf16 helpers ------------------
__device__ __forceinline__ unsigned pack2bf(__nv_bfloat16 a, __nv_bfloat16 b) {
    __nv_bfloat162 t; t.x = a; t.y = b;
    return reinterpret_cast<unsigned&>(t);
}

__device__ __forceinline__ void bsplit2(float x0, float x1, unsigned &hi, unsigned &lo) {
    __nv_bfloat16 h0 = __float2bfloat16(x0);
    __nv_bfloat16 h1 = __float2bfloat16(x1);
    __nv_bfloat16 l0 = __float2bfloat16(x0 - __bfloat162float(h0));
    __nv_bfloat16 l1 = __float2bfloat16(x1 - __bfloat162float(h1));
    hi = pack2bf(h0, h1);
    lo = pack2bf(l0, l1);
}

__device__ __forceinline__ void mma_bf16(float d[4],
                                         unsigned a0, unsigned a1, unsigned a2, unsigned a3,
                                         unsigned b0, unsigned b1)
{
    asm volatile(
        "mma.sync.aligned.m16n8k16.row.col.f32.bf16.bf16.f32 "
        "{%0,%1,%2,%3}, {%4,%5,%6,%7}, {%8,%9}, {%0,%1,%2,%3};\n"
        : "+f"(d[0]), "+f"(d[1]), "+f"(d[2]), "+f"(d[3])
        : "r"(a0), "r"(a1), "r"(a2), "r"(a3), "r"(b0), "r"(b1));
}

__device__ __forceinline__ float fexp2(float x) {
    float y;
    asm("ex2.approx.f32 %0, %1;" : "=f"(y) : "f"(x));
    return y;
}

__device__ __forceinline__ void cp16(void* smem_dst, const void* gmem_src) {
    unsigned s = (unsigned)__cvta_generic_to_shared(smem_dst);
    asm volatile("cp.async.cg.shared.global [%0], [%1], 16;\n"
                 :: "r"(s), "l"(gmem_src) : "memory");
}
#define CP_COMMIT() asm volatile("cp.async.commit_group;\n" ::: "memory")
#define CP_WAIT(n)  asm volatile("cp.async.wait_group %0;\n" :: "n"(n) : "memory")

// ====================================================================
// Prepack kernels
// ====================================================================
__global__ void __launch_bounds__(256) pack_masks(const uint4* __restrict__ a,
                                                  const uint4* __restrict__ b,
                                                  uchar4* __restrict__ oa,
                                                  uchar4* __restrict__ ob)
{
    int i = blockIdx.x * blockDim.x + threadIdx.x;
    uint4 x = a[i];
    oa[i] = make_uchar4(x.x ? 1 : 0, x.y ? 1 : 0, x.z ? 1 : 0, x.w ? 1 : 0);
    uint4 y = b[i];
    ob[i] = make_uchar4(y.x ? 1 : 0, y.y ? 1 : 0, y.z ? 1 : 0, y.w ? 1 : 0);
}

__global__ void __launch_bounds__(256) pack_in(const float4* __restrict__ v,
                                               const float4* __restrict__ k,
                                               const float4* __restrict__ q)
{
    int z = blockIdx.y;
    const float4* src = (z == 0) ? v : (z == 1) ? k : q;
    long i = (long)blockIdx.x * 256 + threadIdx.x;
    float4 x = src[i];
    unsigned h01, l01, h23, l23;
    bsplit2(x.x, x.y, h01, l01);
    bsplit2(x.z, x.w, h23, l23);
    long d = (long)z * (MROWS * (long)HS / 4) + i;
    ((uint2*)g_inhi)[d] = make_uint2(h01, h23);
    ((uint2*)g_inlo)[d] = make_uint2(l01, l23);
}

__global__ void __launch_bounds__(256) pack_w(const float4* __restrict__ w0,
                                              const float4* __restrict__ w1,
                                              const float4* __restrict__ w2,
                                              const float4* __restrict__ w3)
{
    int z = blockIdx.y;
    const float4* src = (z == 0) ? w0 : (z == 1) ? w1 : (z == 2) ? w2 : w3;
    long i = (long)blockIdx.x * 256 + threadIdx.x;
    float4 x = src[i];
    unsigned h01, l01, h23, l23;
    bsplit2(x.x, x.y, h01, l01);
    bsplit2(x.z, x.w, h23, l23);
    long d = (long)z * ((long)HS * HS / 4) + i;
    ((uint2*)g_whi)[d] = make_uint2(h01, h23);
    ((uint2*)g_wlo)[d] = make_uint2(l01, l23);
}

// ====================================================================
// bf16 GEMM (R13 config, GEMM plateau): 128x128 tile, cp.async, 2 CTAs/SM.
// ====================================================================
#define BP 40
#define STG (4*128*BP)

template<int GEMM3>
__global__ void __launch_bounds__(256, 2) gemm_pre(float* __restrict__ Cout,
                                                   int M, int N, int K)
{
    extern __shared__ float smf[];
    __nv_bfloat16* smb = (__nv_bfloat16*)smf;

    const __nv_bfloat16 *Ahi, *Alo, *Whi, *Wlo;
    float* C;
    if (GEMM3) {
        int z = blockIdx.z;
        Ahi = (const __nv_bfloat16*)g_inhi + (long)z * MROWS * HS;
        Alo = (const __nv_bfloat16*)g_inlo + (long)z * MROWS * HS;
        Whi = (const __nv_bfloat16*)g_whi + (long)z * HS * HS;
        Wlo = (const __nv_bfloat16*)g_wlo + (long)z * HS * HS;
        C   = (z == 0) ? g_vh : (z == 1) ? g_kh : g_qh;
    } else {
        Ahi = (const __nv_bfloat16*)g_atthi;
        Alo = (const __nv_bfloat16*)g_attlo;
        Whi = (const __nv_bfloat16*)g_whi + 3L * HS * HS;
        Wlo = (const __nv_bfloat16*)g_wlo + 3L * HS * HS;
        C   = Cout;
    }

    const int tid  = threadIdx.x;
    const int br   = blockIdx.y;
    const int bc   = blockIdx.x;
    const int wid  = tid >> 5;
    const int lane = tid & 31;
    const int g    = lane >> 2;
    const int tig  = lane & 3;
    const int wm   = wid >> 2;
    const int wn   = wid & 3;

    const __nv_bfloat16* AbH = Ahi + (long)br * 128 * K;
    const __nv_bfloat16* AbL = Alo + (long)br * 128 * K;
    const __nv_bfloat16* BbH = Whi + (long)bc * 128 * K;
    const __nv_bfloat16* BbL = Wlo + (long)bc * 128 * K;

    float acc[4][4][4];
#pragma unroll
    for (int mt = 0; mt < 4; ++mt)
#pragma unroll
        for (int nt = 0; nt < 4; ++nt)
#pragma unroll
            for (int r = 0; r < 4; ++r) acc[mt][nt][r] = 0.f;

    auto issue = [&](int s, int kb) {
        __nv_bfloat16* AsHi = smb + s * STG;
        __nv_bfloat16* AsLo = AsHi + 128 * BP;
        __nv_bfloat16* BsHi = AsLo + 128 * BP;
        __nv_bfloat16* BsLo = BsHi + 128 * BP;
#pragma unroll
        for (int i = 0; i < 2; ++i) {
            int ch = tid + i * 256;
            int row = ch >> 2, seg = ch & 3;
            long go = (long)row * K + kb + seg * 8;
            int  so = row * BP + seg * 8;
            cp16(AsHi + so, AbH + go);
            cp16(AsLo + so, AbL + go);
            cp16(BsHi + so, BbH + go);
            cp16(BsLo + so, BbL + go);
        }
        CP_COMMIT();
    };

    issue(0, 0);

    const int nKt = K / 32;
    for (int kt = 0; kt < nKt; ++kt) {
        const int s = kt & 1;
        if (kt + 1 < nKt) {
            issue(s ^ 1, (kt + 1) * 32);
            CP_WAIT(1);
        } else {
            CP_WAIT(0);
        }
        __syncthreads();

        const __nv_bfloat16* AsHi = smb + s * STG;
        const __nv_bfloat16* AsLo = AsHi + 128 * BP;
        const __nv_bfloat16* BsHi = AsLo + 128 * BP;
        const __nv_bfloat16* BsLo = BsHi + 128 * BP;

#pragma unroll
        for (int ks = 0; ks < 2; ++ks) {
            const int kk = ks * 16;
            unsigned ah[4][4], al[4][4];
#pragma unroll
            for (int mt = 0; mt < 4; ++mt) {
                int m = wm * 64 + mt * 16 + g;
                const __nv_bfloat16* pH = AsHi + m * BP + kk + tig * 2;
                const __nv_bfloat16* pL = AsLo + m * BP + kk + tig * 2;
                ah[mt][0] = *(const unsigned*)(pH);
                ah[mt][1] = *(const unsigned*)(pH + 8 * BP);
                ah[mt][2] = *(const unsigned*)(pH + 8);
                ah[mt][3] = *(const unsigned*)(pH + 8 * BP + 8);
                al[mt][0] = *(const unsigned*)(pL);
                al[mt][1] = *(const unsigned*)(pL + 8 * BP);
                al[mt][2] = *(const unsigned*)(pL + 8);
                al[mt][3] = *(const unsigned*)(pL + 8 * BP + 8);
            }
#pragma unroll
            for (int nt = 0; nt < 4; ++nt) {
                int n = wn * 32 + nt * 8 + g;
                const __nv_bfloat16* pH = BsHi + n * BP + kk + tig * 2;
                const __nv_bfloat16* pL = BsLo + n * BP + kk + tig * 2;
                unsigned bh0 = *(const unsigned*)(pH);
                unsigned bh1 = *(const unsigned*)(pH + 8);
                unsigned bl0 = *(const unsigned*)(pL);
                unsigned bl1 = *(const unsigned*)(pL + 8);
#pragma unroll
                for (int mt = 0; mt < 4; ++mt) {
                    mma_bf16(acc[mt][nt], ah[mt][0], ah[mt][1], ah[mt][2], ah[mt][3],
                             bh0, bh1);
                    mma_bf16(acc[mt][nt], al[mt][0], al[mt][1], al[mt][2], al[mt][3],
                             bh0, bh1);
                    mma_bf16(acc[mt][nt], ah[mt][0], ah[mt][1], ah[mt][2], ah[mt][3],
                             bl0, bl1);
                }
            }
        }
        __syncthreads();
    }

#pragma unroll
    for (int mt = 0; mt < 4; ++mt) {
#pragma unroll
        for (int nt = 0; nt < 4; ++nt) {
            int jj = bc * 128 + wn * 32 + nt * 8 + tig * 2;
#pragma unroll
            for (int half = 0; half < 2; ++half) {
                int ii = br * 128 + wm * 64 + mt * 16 + g + half * 8;
                float2 val;
                val.x = acc[mt][nt][half * 2 + 0];
                val.y = acc[mt][nt][half * 2 + 1];
                if (GEMM3 == 0) {
                    *(float2*)(C + (long)ii * N + jj) = val;
                } else {
                    int b = ii >> 9, l = ii & 511;
                    int h = jj >> 6, d = jj & 63;
                    *(float2*)(C + (((long)(b * 16 + h) * 512) + l) * 64 + d) = val;
                }
            }
        }
    }
}

// ====================================================================
// FUSED two-stage tensor-core flash attention (all-bf16 3-term).
// R16: P never touches smem — softmax produces packed bf16 hi/lo P
// fragments in registers (C-frag layout == A-frag layout: nt=2kc,2kc+1);
// softmax runs in exp2 domain (log2e folded into Q scale).
// ====================================================================
#define KP  72
#define VTP 36
#define QSP 68
#define OFF_KHI 0
#define OFF_KLO 2304
#define OFF_VTH 4608
#define OFF_VTL 6912
#define OFF_PQ  9216
#define OFF_MS  18432
#define ATTN_SMEM_FLOATS 20480            // 81920 B

__global__ void __launch_bounds__(256, 1) attn_fused(
    const float* __restrict__ Qg,          // g_qh [B,H,L,D]
    const float* __restrict__ img,         // [B,L,HS]
    const unsigned char* __restrict__ absm8,
    const float* __restrict__ kh,          // [B,H,L,D]
    const float* __restrict__ vh,          // [B,H,L,D]
    const unsigned char* __restrict__ mask8)
{
    extern __shared__ float sm[];
    __nv_bfloat16* Khi = (__nv_bfloat16*)(sm + OFF_KHI);
    __nv_bfloat16* Klo = (__nv_bfloat16*)(sm + OFF_KLO);
    unsigned* VtHi = (unsigned*)(sm + OFF_VTH);
    unsigned* VtLo = (unsigned*)(sm + OFF_VTL);
    float*    Qs   = sm + OFF_PQ;          // Q staging only (pre-loop)
    unsigned char* Ms = (unsigned char*)(sm + OFF_MS);

    const int b  = blockIdx.z;
    const int h  = blockIdx.y;
    const int q0 = blockIdx.x * 128;

    const float* Qp  = Qg + (((long)(b*16 + h) * 512) + q0) * 64;
    const float* Kbase[2];
    const float* Vbase[2];
    const unsigned char* Mbase[2];
    int rstride[2];
    Kbase[0] = img + (long)b * LL * HS + h * 64;   rstride[0] = HS;
    Vbase[0] = Kbase[0];
    Mbase[0] = absm8 + (long)b * LL * LL + (long)q0 * LL;
    Kbase[1] = kh + (((long)(b*16 + h) * 512)) * 64;  rstride[1] = DD;
    Vbase[1] = vh + (((long)(b*16 + h) * 512)) * 64;
    Mbase[1] = mask8 + (long)b * LL * LL + (long)q0 * LL;

    __nv_bfloat16* OHi = (__nv_bfloat16*)g_atthi + (long)b * LL * HS + h * 64 + (long)q0 * HS;
    __nv_bfloat16* OLo = (__nv_bfloat16*)g_attlo + (long)b * LL * HS + h * 64 + (long)q0 * HS;

    const int tid  = threadIdx.x;
    const int w    = tid >> 5;
    const int lane = tid & 31;
    const int g    = lane >> 2;
    const int tig  = lane & 3;
    const int r0   = w * 16 + g;

    const int kf_row[4] = { (tid) >> 4, (tid + 256) >> 4, (tid + 512) >> 4, (tid + 768) >> 4 };
    const int kf_c4 = tid & 15;
    const int vjp0 = tid & 31, vc40 = tid >> 5;
    const int vjp1 = vjp0, vc41 = vc40 + 8;

    // ---- stage Q, extract bf16 hi/lo fragments (QSCALE folded) ----
#pragma unroll
    for (int it = 0; it < 8; ++it) {
        int f = tid + it * 256;
        int row = f >> 4, c4 = f & 15;
        float4 v = *(const float4*)(Qp + (long)row * 64 + c4 * 4);
        float* dst = Qs + row * QSP + c4 * 4;
        dst[0] = v.x; dst[1] = v.y; dst[2] = v.z; dst[3] = v.w;
    }
    __syncthreads();

    unsigned qh[4][4], ql[4][4];
#pragma unroll
    for (int kc = 0; kc < 4; ++kc) {
        const float* p0 = Qs + (r0)     * QSP + kc * 16 + tig * 2;
        const float* p1 = Qs + (r0 + 8) * QSP + kc * 16 + tig * 2;
        bsplit2(p0[0] * QSCALE, p0[1] * QSCALE, qh[kc][0], ql[kc][0]);
        bsplit2(p1[0] * QSCALE, p1[1] * QSCALE, qh[kc][1], ql[kc][1]);
        bsplit2(p0[8] * QSCALE, p0[9] * QSCALE, qh[kc][2], ql[kc][2]);
        bsplit2(p1[8] * QSCALE, p1[9] * QSCALE, qh[kc][3], ql[kc][3]);
    }

    float oacc[8][4];
#pragma unroll
    for (int nt = 0; nt < 8; ++nt)
#pragma unroll
        for (int i = 0; i < 4; ++i) oacc[nt][i] = 0.f;

    float m0 = -1e30f, m1 = -1e30f, l0 = 0.f, l1 = 0.f;

    float4 pk[4];
    float4 pva[2], pvb[2];
    uint4  pm[2];

    auto prefetch = [&](int ph, int k0) {
        const float* Kp = Kbase[ph];
        const float* Vp = Vbase[ph];
        const unsigned char* Mp = Mbase[ph];
        const int rs = rstride[ph];
#pragma unroll
        for (int it = 0; it < 4; ++it)
            pk[it] = *(const float4*)(Kp + (long)(k0 + kf_row[it]) * rs + kf_c4 * 4);
        {
            const float* v0 = Vp + (long)(k0 + 2 * vjp0) * rs + vc40 * 4;
            pva[0] = *(const float4*)v0;
            pvb[0] = *(const float4*)(v0 + rs);
            const float* v1 = Vp + (long)(k0 + 2 * vjp1) * rs + vc41 * 4;
            pva[1] = *(const float4*)v1;
            pvb[1] = *(const float4*)(v1 + rs);
        }
#pragma unroll
        for (int it = 0; it < 2; ++it) {
            int u = tid + it * 256;
            int row = u >> 2, c16 = u & 3;
            pm[it] = *(const uint4*)(Mp + (long)row * LL + k0 + c16 * 16);
        }
    };

    prefetch(0, 0);

    for (int phase = 0; phase < 2; ++phase) {
        for (int kt = 0; kt < 8; ++kt) {
            // ---- store staged tile (cvt from registers) ----
#pragma unroll
            for (int it = 0; it < 4; ++it) {
                int row = kf_row[it];
                unsigned h01, l01, h23, l23;
                bsplit2(pk[it].x, pk[it].y, h01, l01);
                bsplit2(pk[it].z, pk[it].w, h23, l23);
                *(uint2*)(Khi + row * KP + kf_c4 * 4) = make_uint2(h01, h23);
                *(uint2*)(Klo + row * KP + kf_c4 * 4) = make_uint2(l01, l23);
            }
#pragma unroll
            for (int it = 0; it < 2; ++it) {
                int jp = (it == 0) ? vjp0 : vjp1;
                int c4 = (it == 0) ? vc40 : vc41;
                float4 a = pva[it], bq = pvb[it];
                unsigned hh, ll;
                bsplit2(a.x, bq.x, hh, ll);
                VtHi[(c4 * 4 + 0) * VTP + jp] = hh; VtLo[(c4 * 4 + 0) * VTP + jp] = ll;
                bsplit2(a.y, bq.y, hh, ll);
                VtHi[(c4 * 4 + 1) * VTP + jp] = hh; VtLo[(c4 * 4 + 1) * VTP + jp] = ll;
                bsplit2(a.z, bq.z, hh, ll);
                VtHi[(c4 * 4 + 2) * VTP + jp] = hh; VtLo[(c4 * 4 + 2) * VTP + jp] = ll;
                bsplit2(a.w, bq.w, hh, ll);
                VtHi[(c4 * 4 + 3) * VTP + jp] = hh; VtLo[(c4 * 4 + 3) * VTP + jp] = ll;
            }
#pragma unroll
            for (int it = 0; it < 2; ++it) {
                int u = tid + it * 256;
                int row = u >> 2, c16 = u & 3;
                ((uint4*)Ms)[row * 4 + c16] = pm[it];
            }
            __syncthreads();

            // ---- prefetch next tile (possibly next phase) ----
            if (kt + 1 < 8)          prefetch(phase, (kt + 1) * 64);
            else if (phase == 0)     prefetch(1, 0);

            // ---- S = Q K^T (3-term bf16, exp2 domain) ----
            float sacc[8][4];
#pragma unroll
            for (int nt = 0; nt < 8; ++nt) {
#pragma unroll
                for (int i = 0; i < 4; ++i) sacc[nt][i] = 0.f;
#pragma unroll
                for (int kc = 0; kc < 4; ++kc) {
                    const __nv_bfloat16* pH = Khi + (nt * 8 + g) * KP + kc * 16 + tig * 2;
                    const __nv_bfloat16* pL = Klo + (nt * 8 + g) * KP + kc * 16 + tig * 2;
                    unsigned bh0 = *(const unsigned*)(pH);
                    unsigned bh1 = *(const unsigned*)(pH + 8);
                    unsigned bl0 = *(const unsigned*)(pL);
                    unsigned bl1 = *(const unsigned*)(pL + 8);
                    mma_bf16(sacc[nt], qh[kc][0], qh[kc][1], qh[kc][2], qh[kc][3], bh0, bh1);
                    mma_bf16(sacc[nt], ql[kc][0], ql[kc][1], ql[kc][2], ql[kc][3], bh0, bh1);
                    mma_bf16(sacc[nt], qh[kc][0], qh[kc][1], qh[kc][2], qh[kc][3], bl0, bl1);
                }
            }

            // ---- mask ----
#pragma unroll
            for (int nt = 0; nt < 8; ++nt) {
                uchar2 mA = *(const uchar2*)(Ms + (r0)     * 64 + nt * 8 + tig * 2);
                uchar2 mB = *(const uchar2*)(Ms + (r0 + 8) * 64 + nt * 8 + tig * 2);
                if (mA.x) sacc[nt][0] = -1e9f;
                if (mA.y) sacc[nt][1] = -1e9f;
                if (mB.x) sacc[nt][2] = -1e9f;
                if (mB.y) sacc[nt][3] = -1e9f;
            }

            // ---- online softmax (warp-local, exp2) ----
            float mx0 = -3.0e38f, mx1 = -3.0e38f;
#pragma unroll
            for (int nt = 0; nt < 8; ++nt) {
                mx0 = fmaxf(mx0, fmaxf(sacc[nt][0], sacc[nt][1]));
                mx1 = fmaxf(mx1, fmaxf(sacc[nt][2], sacc[nt][3]));
            }
            mx0 = fmaxf(mx0, __shfl_xor_sync(0xffffffffu, mx0, 1));
            mx0 = fmaxf(mx0, __shfl_xor_sync(0xffffffffu, mx0, 2));
            mx1 = fmaxf(mx1, __shfl_xor_sync(0xffffffffu, mx1, 1));
            mx1 = fmaxf(mx1, __shfl_xor_sync(0xffffffffu, mx1, 2));

            float mn0 = fmaxf(m0, mx0), mn1 = fmaxf(m1, mx1);
            float al0 = fexp2(m0 - mn0), al1 = fexp2(m1 - mn1);
            m0 = mn0; m1 = mn1;

            // ---- P: registers only (C-frag layout == A-frag layout) ----
            unsigned pfh[8][2], pfl[8][2];
            float sum0 = 0.f, sum1 = 0.f;
#pragma unroll
            for (int nt = 0; nt < 8; ++nt) {
                float p00 = fexp2(sacc[nt][0] - m0);
                float p01 = fexp2(sacc[nt][1] - m0);
                float p10 = fexp2(sacc[nt][2] - m1);
                float p11 = fexp2(sacc[nt][3] - m1);
                sum0 += p00 + p01;
                sum1 += p10 + p11;
                bsplit2(p00, p01, pfh[nt][0], pfl[nt][0]);
                bsplit2(p10, p11, pfh[nt][1], pfl[nt][1]);
            }
            sum0 += __shfl_xor_sync(0xffffffffu, sum0, 1);
            sum0 += __shfl_xor_sync(0xffffffffu, sum0, 2);
            sum1 += __shfl_xor_sync(0xffffffffu, sum1, 1);
            sum1 += __shfl_xor_sync(0xffffffffu, sum1, 2);
            l0 = l0 * al0 + sum0;
            l1 = l1 * al1 + sum1;

#pragma unroll
            for (int nt = 0; nt < 8; ++nt) {
                oacc[nt][0] *= al0; oacc[nt][1] *= al0;
                oacc[nt][2] *= al1; oacc[nt][3] *= al1;
            }

            // ---- O += P V (3-term bf16, P from registers) ----
#pragma unroll
            for (int kc = 0; kc < 4; ++kc) {
                unsigned ph0 = pfh[2*kc][0],   ph1 = pfh[2*kc][1];
                unsigned ph2 = pfh[2*kc+1][0], ph3 = pfh[2*kc+1][1];
                unsigned pl0 = pfl[2*kc][0],   pl1 = pfl[2*kc][1];
                unsigned pl2 = pfl[2*kc+1][0], pl3 = pfl[2*kc+1][1];
#pragma unroll
                for (int nt = 0; nt < 8; ++nt) {
                    const unsigned* vH = VtHi + (nt * 8 + g) * VTP + kc * 8 + tig;
                    const unsigned* vL = VtLo + (nt * 8 + g) * VTP + kc * 8 + tig;
                    unsigned bh0 = vH[0], bh1 = vH[4];
                    unsigned bl0 = vL[0], bl1 = vL[4];
                    mma_bf16(oacc[nt], ph0, ph1, ph2, ph3, bh0, bh1);
                    mma_bf16(oacc[nt], pl0, pl1, pl2, pl3, bh0, bh1);
                    mma_bf16(oacc[nt], ph0, ph1, ph2, ph3, bl0, bl1);
                }
            }
            __syncthreads();
        }

        if (phase == 0) {
            // ---- inter-stage: qn = oacc/l + Q residual, rebuild Q frags ----
            float inv0 = 1.0f / l0, inv1 = 1.0f / l1;
            float qn0[8][2], qn1[8][2];
#pragma unroll
            for (int nt = 0; nt < 8; ++nt) {
                int c = nt * 8 + tig * 2;
                float2 qr0 = *(const float2*)(Qp + (long)(r0)     * 64 + c);
                float2 qr1 = *(const float2*)(Qp + (long)(r0 + 8) * 64 + c);
                qn0[nt][0] = oacc[nt][0] * inv0 + qr0.x;
                qn0[nt][1] = oacc[nt][1] * inv0 + qr0.y;
                qn1[nt][0] = oacc[nt][2] * inv1 + qr1.x;
                qn1[nt][1] = oacc[nt][3] * inv1 + qr1.y;
            }
#pragma unroll
            for (int kc = 0; kc < 4; ++kc) {
                bsplit2(qn0[2*kc][0]   * QSCALE, qn0[2*kc][1]   * QSCALE, qh[kc][0], ql[kc][0]);
                bsplit2(qn1[2*kc][0]   * QSCALE, qn1[2*kc][1]   * QSCALE, qh[kc][1], ql[kc][1]);
                bsplit2(qn0[2*kc+1][0] * QSCALE, qn0[2*kc+1][1] * QSCALE, qh[kc][2], ql[kc][2]);
                bsplit2(qn1[2*kc+1][0] * QSCALE, qn1[2*kc+1][1] * QSCALE, qh[kc][3], ql[kc][3]);
            }
            m0 = -1e30f; m1 = -1e30f; l0 = 0.f; l1 = 0.f;
#pragma unroll
            for (int nt = 0; nt < 8; ++nt)
#pragma unroll
                for (int i = 0; i < 4; ++i) oacc[nt][i] = 0.f;
        }
    }

    // ---- epilogue: bf16 hi/lo to g_att{hi,lo} [B,L,H*D] ----
    float inv0 = 1.0f / l0, inv1 = 1.0f / l1;
#pragma unroll
    for (int nt = 0; nt < 8; ++nt) {
        int c = nt * 8 + tig * 2;
        unsigned hh, ll;
        bsplit2(oacc[nt][0] * inv0, oacc[nt][1] * inv0, hh, ll);
        *(unsigned*)(OHi + (long)(r0) * HS + c) = hh;
        *(unsigned*)(OLo + (long)(r0) * HS + c) = ll;
        bsplit2(oacc[nt][2] * inv1, oacc[nt][3] * inv1, hh, ll);
        *(unsigned*)(OHi + (long)(r0 + 8) * HS + c) = hh;
        *(unsigned*)(OLo + (long)(r0 + 8) * HS + c) = ll;
    }
}

// ====================================================================
extern "C" void kernel_launch(void* const* d_in, const int* in_sizes, int n_in,
                              void* d_out, int out_size)
{
    (void)in_sizes; (void)n_in; (void)out_size;
    const float* v   = (const float*)d_in[0];
    const float* k   = (const float*)d_in[1];
    const float* q   = (const float*)d_in[2];
    const float* img = (const float*)d_in[3];
    const float* Wv  = (const float*)d_in[4];
    const float* Wk  = (const float*)d_in[5];
    const float* Wq  = (const float*)d_in[6];
    const float* Wm  = (const float*)d_in[7];
    const uint4* absm = (const uint4*)d_in[8];
    const uint4* mask = (const uint4*)d_in[9];
    float* out = (float*)d_out;

    float *vh, *kh, *qh;
    unsigned char *absm8, *mask8;
    cudaGetSymbolAddress((void**)&vh,  g_vh);
    cudaGetSymbolAddress((void**)&kh,  g_kh);
    cudaGetSymbolAddress((void**)&qh,  g_qh);
    cudaGetSymbolAddress((void**)&absm8, g_absm8);
    cudaGetSymbolAddress((void**)&mask8, g_mask8);

    pack_masks<<<4096, 256>>>(absm, mask, (uchar4*)absm8, (uchar4*)mask8);
    dim3 gi(MROWS * HS / 4 / 256, 3);
    pack_in<<<gi, 256>>>((const float4*)v, (const float4*)k, (const float4*)q);
    dim3 gw(HS * HS / 4 / 256, 4);
    pack_w<<<gw, 256>>>((const float4*)Wv, (const float4*)Wk,
                        (const float4*)Wq, (const float4*)Wm);

    const int gsmem = 2 * STG * (int)sizeof(__nv_bfloat16);   // 81920
    cudaFuncSetAttribute(gemm_pre<0>,
                         cudaFuncAttributeMaxDynamicSharedMemorySize, gsmem);
    cudaFuncSetAttribute(gemm_pre<1>,
                         cudaFuncAttributeMaxDynamicSharedMemorySize, gsmem);

    dim3 g3(HS / 128, MROWS / 128, 3);   // (8, 64, 3)
    gemm_pre<1><<<g3, 256, gsmem>>>(nullptr, MROWS, HS, HS);

    const int asmem = ATTN_SMEM_FLOATS * (int)sizeof(float);
    cudaFuncSetAttribute(attn_fused,
                         cudaFuncAttributeMaxDynamicSharedMemorySize, asmem);

    dim3 ga(LL / 128, HH, BB);   // (4, 16, 16)
    attn_fused<<<ga, 256, asmem>>>(qh, img, absm8, kh, vh, mask8);

    dim3 gg(HS / 128, MROWS / 128);   // (8, 64)
    gemm_pre<0><<<gg, 256, gsmem>>>(out, MROWS, HS, HS);
}